// round 11
// baseline (speedup 1.0000x reference)
#include <cuda_runtime.h>
#include <cuda_fp16.h>
#include <math.h>
#include <stdint.h>

#define BATCH   16
#define CH      256
#define TOKENS  (BATCH*64*64)      // 65536
#define HID     1024
#define NHEAD   8
#define NTOK    64

// ---------------- scratch (device globals; allocation-free) ----------------
__device__ float  g_xf  [TOKENS*CH];   // shortcut, token-major (fp32)
__device__ float  g_xf2 [TOKENS*CH];   // after proj residual, token-major (fp32)
__device__ float  g_bias[NHEAD*NTOK*NTOK];

__device__ __half g_xnw_h[TOKENS*CH];  // LN1 out, windowed
__device__ __half g_q   [TOKENS*CH];   // [win][head][pos][hd], pre-scaled
__device__ __half g_k   [TOKENS*CH];
__device__ __half g_v   [TOKENS*CH];
__device__ __half g_img_h[TOKENS*CH];  // folded image NHWC
__device__ __half g_att_h[TOKENS*CH];  // attn out; gaze accumulates in-place
__device__ __half g_ln2_h[TOKENS*CH];
__device__ __half g_h1_h [TOKENS*HID];

__device__ __half w_qkv [768*256];
__device__ __half w_proj[256*256];
__device__ __half w_fc1 [1024*256];
__device__ __half w_fc2 [256*1024];

// ============================ helpers ============================
__device__ __forceinline__ uint32_t smem_u32(const void* p) {
    uint32_t a;
    asm("{ .reg .u64 t; cvta.to.shared.u64 t, %1; cvt.u32.u64 %0, t; }" : "=r"(a) : "l"(p));
    return a;
}
__device__ __forceinline__ uint32_t f2h2(float a, float b) {
    __half2 h = __floats2half2_rn(a, b);
    return *reinterpret_cast<uint32_t*>(&h);
}
__device__ __forceinline__ void ldsm4(uint32_t (&r)[4], uint32_t addr) {
    asm volatile("ldmatrix.sync.aligned.m8n8.x4.shared.b16 {%0,%1,%2,%3}, [%4];"
                 : "=r"(r[0]), "=r"(r[1]), "=r"(r[2]), "=r"(r[3]) : "r"(addr));
}
__device__ __forceinline__ void ldsm4t(uint32_t (&r)[4], uint32_t addr) {
    asm volatile("ldmatrix.sync.aligned.m8n8.x4.trans.shared.b16 {%0,%1,%2,%3}, [%4];"
                 : "=r"(r[0]), "=r"(r[1]), "=r"(r[2]), "=r"(r[3]) : "r"(addr));
}
__device__ __forceinline__ void mma16816(float* d, const uint32_t* a, uint32_t b0, uint32_t b1) {
    asm volatile("mma.sync.aligned.m16n8k16.row.col.f32.f16.f16.f32 "
                 "{%0,%1,%2,%3},{%4,%5,%6,%7},{%8,%9},{%0,%1,%2,%3};"
                 : "+f"(d[0]), "+f"(d[1]), "+f"(d[2]), "+f"(d[3])
                 : "r"(a[0]), "r"(a[1]), "r"(a[2]), "r"(a[3]), "r"(b0), "r"(b1));
}
__device__ __forceinline__ void mma16816h(uint32_t* d, const uint32_t* a, uint32_t b0, uint32_t b1) {
    asm volatile("mma.sync.aligned.m16n8k16.row.col.f16.f16.f16.f16 "
                 "{%0,%1},{%2,%3,%4,%5},{%6,%7},{%0,%1};"
                 : "+r"(d[0]), "+r"(d[1])
                 : "r"(a[0]), "r"(a[1]), "r"(a[2]), "r"(a[3]), "r"(b0), "r"(b1));
}
#define CP_A16(dst, src) asm volatile("cp.async.cg.shared.global [%0], [%1], 16;" :: "r"(dst), "l"(src))
#define CP_COMMIT()      asm volatile("cp.async.commit_group;")
#define CP_WAIT(n)       asm volatile("cp.async.wait_group %0;" :: "n"(n))

// ============================ fp16 GEMM, cp.async 3-stage, f16 accumulators ============================
// C[m][n] = sum_k A[m][k]*W[n][k].  BM=128, BN=256, BK=32, 256 thr (2x4 warps), warp tile 64x64.
#define LDSTR 40
#define STG_B 30720                       // bytes per stage: (128+256)*40*2
#define OFF_B 10240                       // B offset within stage (128*40*2)
#define SMEM_DYN (3*STG_B)                // 92160 bytes

template <class Epi>
__global__ __launch_bounds__(256, 2) void hgemm(const __half* __restrict__ A,
                                                const __half* __restrict__ W,
                                                int K, Epi epi) {
    extern __shared__ __half sm[];
    int tid = threadIdx.x, lane = tid & 31, wid = tid >> 5;
    int wm = wid >> 2, wn = wid & 3;
    int bm = blockIdx.y << 7, bn = blockIdx.x << 8;
    int NC = K >> 5;
    uint32_t smb = smem_u32(sm);

    auto issue = [&](int st, int ic) {
        int k0 = ic << 5;
        uint32_t sb = smb + st * STG_B;
        #pragma unroll
        for (int j = 0; j < 2; j++) {
            int ch = tid + (j << 8);
            int row = ch >> 2, cq = ch & 3;
            CP_A16(sb + (row * LDSTR + cq * 8) * 2, A + (size_t)(bm + row) * K + k0 + cq * 8);
        }
        #pragma unroll
        for (int j = 0; j < 4; j++) {
            int ch = tid + (j << 8);
            int row = ch >> 2, cq = ch & 3;
            CP_A16(sb + OFF_B + (row * LDSTR + cq * 8) * 2, W + (size_t)(bn + row) * K + k0 + cq * 8);
        }
        CP_COMMIT();
    };

    issue(0, 0); issue(1, 1);
    uint32_t acch[4][8][2] = {};
    for (int ic = 0; ic < NC; ic++) {
        if (ic + 1 < NC) CP_WAIT(1); else CP_WAIT(0);
        __syncthreads();
        if (ic + 2 < NC) issue((ic + 2) % 3, ic + 2);
        uint32_t baseA = smb + (ic % 3) * STG_B;
        uint32_t baseB = baseA + OFF_B;
        #pragma unroll
        for (int ks = 0; ks < 2; ks++) {
            uint32_t af[4][4], bf[4][4];
            #pragma unroll
            for (int mt = 0; mt < 4; mt++)
                ldsm4(af[mt], baseA + (((wm*64 + mt*16 + (lane & 15)) * LDSTR + ks*16 + (lane >> 4)*8) << 1));
            #pragma unroll
            for (int bt = 0; bt < 4; bt++)
                ldsm4(bf[bt], baseB + (((wn*64 + bt*16 + (lane & 15)) * LDSTR + ks*16 + (lane >> 4)*8) << 1));
            #pragma unroll
            for (int mt = 0; mt < 4; mt++)
                #pragma unroll
                for (int bt = 0; bt < 4; bt++) {
                    mma16816h(acch[mt][2*bt],     af[mt], bf[bt][0], bf[bt][2]);
                    mma16816h(acch[mt][2*bt + 1], af[mt], bf[bt][1], bf[bt][3]);
                }
        }
    }
    int g = lane >> 2, tg = lane & 3;

    if constexpr (Epi::STAGED) {
        // FC2 (N=256, bn=0): val = acc + bias + xf2, NCHW-coalesced via 4 passes of 32 rows
        float* stg = (float*)sm;
        int b = bm >> 12, hw0 = bm & 4095;
        for (int p = 0; p < 4; p++) {
            __syncthreads();
            if (wm == (p >> 1)) {
                int m0 = (p & 1) * 2;
                #pragma unroll
                for (int dm = 0; dm < 2; dm++) {
                    int mt = m0 + dm;
                    int lr = dm * 16 + g;                        // local row 0..23 (+8 → 0..31)
                    size_t gr0 = (size_t)(bm + p * 32 + lr) * CH;
                    size_t gr1 = gr0 + 8 * CH;
                    #pragma unroll
                    for (int nt = 0; nt < 8; nt++) {
                        int c = wn * 64 + nt * 8 + tg * 2;
                        __half2 h0 = *(__half2*)&acch[mt][nt][0];
                        __half2 h1 = *(__half2*)&acch[mt][nt][1];
                        float2 x0 = *(const float2*)&g_xf2[gr0 + c];
                        float2 x1 = *(const float2*)&g_xf2[gr1 + c];
                        stg[lr * 258 + c]           = __low2float(h0)  + epi.bias[c]     + x0.x;
                        stg[lr * 258 + c + 1]       = __high2float(h0) + epi.bias[c + 1] + x0.y;
                        stg[(lr + 8) * 258 + c]     = __low2float(h1)  + epi.bias[c]     + x1.x;
                        stg[(lr + 8) * 258 + c + 1] = __high2float(h1) + epi.bias[c + 1] + x1.y;
                    }
                }
            }
            __syncthreads();
            #pragma unroll 1
            for (int i = 0; i < 32; i++) {
                int idx = tid + (i << 8);
                int row = idx & 31, c = idx >> 5;
                epi.out[((size_t)(b * CH + c) << 12) + hw0 + p * 32 + row] = stg[row * 258 + c];
            }
        }
    } else {
        #pragma unroll
        for (int mt = 0; mt < 4; mt++) {
            int M0 = bm + wm * 64 + mt * 16;
            #pragma unroll
            for (int nt = 0; nt < 8; nt++) {
                int N0 = bn + wn * 64 + nt * 8 + tg * 2;
                __half2 h0 = *(__half2*)&acch[mt][nt][0];
                __half2 h1 = *(__half2*)&acch[mt][nt][1];
                epi.pair(M0 + g,     N0, __low2float(h0), __high2float(h0));
                epi.pair(M0 + g + 8, N0, __low2float(h1), __high2float(h1));
            }
        }
    }
}

// ============================ epilogues (pair interface: c even) ============================
struct EpiQKV {
    const float* bias;
    static constexpr bool STAGED = false;
    __device__ void pair(int r, int c, float a0, float a1) const {
        float va = a0 + bias[c], vb = a1 + bias[c + 1];
        int part = c >> 8, head = (c >> 5) & 7, d = c & 31;
        int win = r >> 6, pos = r & 63;
        size_t o = (size_t)(win * NHEAD + head) * 2048 + pos * 32 + d;
        if (part == 0)      *(uint32_t*)&g_q[o] = f2h2(va * 4.0f, vb * 4.0f);
        else if (part == 1) *(uint32_t*)&g_k[o] = f2h2(va, vb);
        else {
            uint32_t hv = f2h2(va, vb);
            *(uint32_t*)&g_v[o] = hv;
            int b = win >> 6, wh = (win >> 3) & 7, ww = win & 7;
            int ii = pos >> 3, jj = pos & 7;
            int R = ii * 8 + wh, Cc = jj * 8 + ww;
            *(uint32_t*)&g_img_h[(((size_t)((b << 6) + R) << 6) + Cc) * CH + (c - 512)] = hv;
        }
    }
};
struct EpiProj {
    const float* bias;
    static constexpr bool STAGED = false;
    __device__ void pair(int r, int c, float a0, float a1) const {
        int win = r >> 6, pos = r & 63;
        int b = win >> 6, wh = (win >> 3) & 7, ww = win & 7;
        int ii = pos >> 3, jj = pos & 7;
        int t = (b << 12) + ((wh * 8 + ii) << 6) + ww * 8 + jj;
        size_t o = (size_t)t * CH + c;
        float2 xf = *(const float2*)&g_xf[o];
        float2 res = make_float2(xf.x + a0 + bias[c], xf.y + a1 + bias[c + 1]);
        *(float2*)&g_xf2[o] = res;
    }
};
struct EpiFC1 {
    const float* bias;
    static constexpr bool STAGED = false;
    __device__ void pair(int r, int c, float a0, float a1) const {
        float x0 = a0 + bias[c], x1 = a1 + bias[c + 1];
        float g0 = 0.5f * x0 * (1.0f + erff(x0 * 0.70710678118654752f));
        float g1 = 0.5f * x1 * (1.0f + erff(x1 * 0.70710678118654752f));
        *(uint32_t*)&g_h1_h[(size_t)r * HID + c] = f2h2(g0, g1);
    }
};
struct EpiFC2 {
    const float* bias;
    float* out;
    static constexpr bool STAGED = true;
    __device__ void pair(int, int, float, float) const {}
};

// ---------------- all weights fp32 -> fp16, one vectorized launch ----------------
__global__ __launch_bounds__(256) void cvt_all(const float* __restrict__ qkv,
                                               const float* __restrict__ proj,
                                               const float* __restrict__ fc1,
                                               const float* __restrict__ fc2) {
    int i4 = blockIdx.x * 256 + threadIdx.x;    // 196608 float4 units
    int i = i4 * 4;
    const float* s;
    __half* d;
    if (i < 196608)      { s = qkv  + i;          d = w_qkv  + i; }
    else if (i < 262144) { s = proj + (i-196608); d = w_proj + (i-196608); }
    else if (i < 524288) { s = fc1  + (i-262144); d = w_fc1  + (i-262144); }
    else                 { s = fc2  + (i-524288); d = w_fc2  + (i-524288); }
    float4 v = *(const float4*)s;
    uint2 h;
    h.x = f2h2(v.x, v.y);
    h.y = f2h2(v.z, v.w);
    *(uint2*)d = h;
}

// ---------------- relative position bias prep ----------------
__global__ void bias_kernel(const float* __restrict__ rpb) {
    int idx = blockIdx.x * 256 + threadIdx.x;
    int h_ = idx >> 12, n = (idx >> 6) & 63, m = idx & 63;
    int di = (n >> 3) - (m >> 3) + 7;
    int dj = (n & 7) - (m & 7) + 7;
    g_bias[idx] = rpb[(di * 15 + dj) * NHEAD + h_];
}

// ---------------- LayerNorm 1 ----------------
__global__ __launch_bounds__(256) void ln1_kernel(const float* __restrict__ x,
                                                  const float* __restrict__ gw,
                                                  const float* __restrict__ gb) {
    __shared__ float tx[256][33];
    int t0 = blockIdx.x * 32;
    int b = t0 >> 12, hw0 = t0 & 4095;
    int tid = threadIdx.x;
    #pragma unroll
    for (int j = 0; j < 32; j++) {
        int idx = j * 256 + tid;
        int c = idx >> 5, i = idx & 31;
        tx[c][i] = x[((size_t)(b * CH + c) << 12) + hw0 + i];
    }
    __syncthreads();
    int lane = tid & 31, w = tid >> 5;
    #pragma unroll
    for (int q = 0; q < 4; q++) {
        int i = w * 4 + q;
        float s = 0.f, s2 = 0.f;
        #pragma unroll
        for (int k = 0; k < 8; k++) { float v = tx[lane + 32 * k][i]; s += v; s2 += v * v; }
        #pragma unroll
        for (int o = 16; o; o >>= 1) { s += __shfl_xor_sync(~0u, s, o); s2 += __shfl_xor_sync(~0u, s2, o); }
        float mean = s * (1.f / CH);
        float inv = rsqrtf(s2 * (1.f / CH) - mean * mean + 1e-5f);
        int t = t0 + i;
        int hw = hw0 + i, hh = hw >> 6, wc = hw & 63;
        int wh = hh >> 3, ii = hh & 7, ww = wc >> 3, jj = wc & 7;
        int r = ((b * 64 + wh * 8 + ww) << 6) + (ii << 3) + jj;
        #pragma unroll
        for (int k = 0; k < 8; k++) {
            int c = lane + 32 * k;
            float v = tx[c][i];
            g_xf[(size_t)t * CH + c] = v;
            g_xnw_h[(size_t)r * CH + c] = __float2half((v - mean) * inv * gw[c] + gb[c]);
        }
    }
}

// ---------------- LayerNorm 2 ----------------
__global__ __launch_bounds__(256) void ln2_kernel(const float* __restrict__ gw,
                                                  const float* __restrict__ gb) {
    int t = blockIdx.x, c = threadIdx.x;
    float val = g_xf2[(size_t)t * CH + c];
    __shared__ float sh1[8], sh2[8], sres[2];
    float s = val, s2 = val * val;
    #pragma unroll
    for (int o = 16; o; o >>= 1) { s += __shfl_xor_sync(~0u, s, o); s2 += __shfl_xor_sync(~0u, s2, o); }
    int lane = c & 31, wrp = c >> 5;
    if (!lane) { sh1[wrp] = s; sh2[wrp] = s2; }
    __syncthreads();
    if (!wrp) {
        s = lane < 8 ? sh1[lane] : 0.f;
        s2 = lane < 8 ? sh2[lane] : 0.f;
        #pragma unroll
        for (int o = 4; o; o >>= 1) { s += __shfl_xor_sync(~0u, s, o); s2 += __shfl_xor_sync(~0u, s2, o); }
        if (!lane) { sres[0] = s; sres[1] = s2; }
    }
    __syncthreads();
    float mean = sres[0] * (1.f / CH);
    float var = sres[1] * (1.f / CH) - mean * mean;
    g_ln2_h[(size_t)t * CH + c] = __float2half((val - mean) * rsqrtf(var + 1e-5f) * gw[c] + gb[c]);
}

// ---------------- tensor-core attention: one block per (win, head), 4 warps ----------------
__global__ __launch_bounds__(128) void attn_mma() {
    int win = blockIdx.x >> 3, head = blockIdx.x & 7;
    __shared__ __half sq[64 * 40], sk[64 * 40], sv[64 * 40];
    __shared__ float sb[64 * 64];
    int tid = threadIdx.x, lane = tid & 31, w = tid >> 5;

    const __half* qb = g_q + (size_t)(win * NHEAD + head) * 2048;
    const __half* kb = g_k + (size_t)(win * NHEAD + head) * 2048;
    const __half* vb = g_v + (size_t)(win * NHEAD + head) * 2048;
    #pragma unroll
    for (int j = 0; j < 2; j++) {
        int ch = tid + (j << 7);
        int row = ch >> 2, cq = ch & 3;
        *(uint4*)&sq[row * 40 + cq * 8] = *(const uint4*)(qb + row * 32 + cq * 8);
        *(uint4*)&sk[row * 40 + cq * 8] = *(const uint4*)(kb + row * 32 + cq * 8);
        *(uint4*)&sv[row * 40 + cq * 8] = *(const uint4*)(vb + row * 32 + cq * 8);
    }
    const float4* bb = (const float4*)(g_bias + head * 4096);
    #pragma unroll
    for (int j = 0; j < 8; j++)
        ((float4*)sb)[tid + (j << 7)] = bb[tid + (j << 7)];
    __syncthreads();

    uint32_t bq = smem_u32(sq), bk = smem_u32(sk), bv = smem_u32(sv);
    int g = lane >> 2, tg = lane & 3;

    uint32_t aq[2][4];
    #pragma unroll
    for (int t = 0; t < 2; t++)
        ldsm4(aq[t], bq + (((16 * w + (lane & 15)) * 40 + t * 16 + (lane >> 4) * 8) << 1));

    float acc[8][4] = {};
    #pragma unroll
    for (int t = 0; t < 2; t++)
        #pragma unroll
        for (int u = 0; u < 4; u++) {
            uint32_t bf[4];
            ldsm4(bf, bk + (((16 * u + (lane & 15)) * 40 + t * 16 + (lane >> 4) * 8) << 1));
            mma16816(acc[2 * u],     aq[t], bf[0], bf[2]);
            mma16816(acc[2 * u + 1], aq[t], bf[1], bf[3]);
        }

    int r0 = 16 * w + g, r1 = r0 + 8;
    float mx0 = -1e30f, mx1 = -1e30f;
    #pragma unroll
    for (int s = 0; s < 8; s++) {
        acc[s][0] += sb[r0 * 64 + 8 * s + tg * 2];
        acc[s][1] += sb[r0 * 64 + 8 * s + tg * 2 + 1];
        acc[s][2] += sb[r1 * 64 + 8 * s + tg * 2];
        acc[s][3] += sb[r1 * 64 + 8 * s + tg * 2 + 1];
        mx0 = fmaxf(mx0, fmaxf(acc[s][0], acc[s][1]));
        mx1 = fmaxf(mx1, fmaxf(acc[s][2], acc[s][3]));
    }
    mx0 = fmaxf(mx0, __shfl_xor_sync(~0u, mx0, 1)); mx0 = fmaxf(mx0, __shfl_xor_sync(~0u, mx0, 2));
    mx1 = fmaxf(mx1, __shfl_xor_sync(~0u, mx1, 1)); mx1 = fmaxf(mx1, __shfl_xor_sync(~0u, mx1, 2));
    float sm0 = 0.f, sm1 = 0.f;
    #pragma unroll
    for (int s = 0; s < 8; s++) {
        acc[s][0] = __expf(acc[s][0] - mx0); acc[s][1] = __expf(acc[s][1] - mx0);
        acc[s][2] = __expf(acc[s][2] - mx1); acc[s][3] = __expf(acc[s][3] - mx1);
        sm0 += acc[s][0] + acc[s][1];
        sm1 += acc[s][2] + acc[s][3];
    }
    sm0 += __shfl_xor_sync(~0u, sm0, 1); sm0 += __shfl_xor_sync(~0u, sm0, 2);
    sm1 += __shfl_xor_sync(~0u, sm1, 1); sm1 += __shfl_xor_sync(~0u, sm1, 2);
    float iv0 = 1.f / sm0, iv1 = 1.f / sm1;
    uint32_t ap[4][4];
    #pragma unroll
    for (int t = 0; t < 4; t++) {
        ap[t][0] = f2h2(acc[2*t][0]*iv0,   acc[2*t][1]*iv0);
        ap[t][1] = f2h2(acc[2*t][2]*iv1,   acc[2*t][3]*iv1);
        ap[t][2] = f2h2(acc[2*t+1][0]*iv0, acc[2*t+1][1]*iv0);
        ap[t][3] = f2h2(acc[2*t+1][2]*iv1, acc[2*t+1][3]*iv1);
    }

    float oacc[4][4] = {};
    #pragma unroll
    for (int t = 0; t < 4; t++)
        #pragma unroll
        for (int np = 0; np < 2; np++) {
            uint32_t bf[4];
            ldsm4t(bf, bv + (((16 * t + (lane & 15)) * 40 + np * 16 + (lane >> 4) * 8) << 1));
            mma16816(oacc[2 * np],     ap[t], bf[0], bf[1]);
            mma16816(oacc[2 * np + 1], ap[t], bf[2], bf[3]);
        }

    __half* ob = g_att_h + ((size_t)win * 64) * 256 + head * 32;
    #pragma unroll
    for (int n = 0; n < 4; n++) {
        *(uint32_t*)&ob[(size_t)r0 * 256 + 8 * n + tg * 2] = f2h2(oacc[n][0], oacc[n][1]);
        *(uint32_t*)&ob[(size_t)r1 * 256 + 8 * n + tg * 2] = f2h2(oacc[n][2], oacc[n][3]);
    }
}

// ---------------- depthwise 9x9 conv + unfold; accumulates into g_att_h in place ----------------
__global__ __launch_bounds__(256) void gaze_conv_kernel(const float* __restrict__ gw,
                                                        const float* __restrict__ gb) {
    int bidx = blockIdx.x;                 // 16*64*8
    int cc = bidx & 7;
    int tile = (bidx >> 3) & 63;
    int b = bidx >> 9;
    int tr = (tile >> 3) << 3;
    int tc = (tile & 7) << 3;
    int ch0 = cc << 5;

    __shared__ float sin_[16][16][32];
    __shared__ float swt[81][32];
    int tid = threadIdx.x;

    for (int i = tid; i < 81 * 32; i += 256) {
        int tap = i >> 5, ch = i & 31;
        swt[tap][ch] = gw[tap * CH + ch0 + ch];
    }
    for (int i = tid; i < 16 * 16 * 32; i += 256) {
        int ch = i & 31, px = (i >> 5) & 15, py = i >> 9;
        int R = tr - 4 + py, Cc = tc - 4 + px;
        float v = 0.f;
        if (R >= 0 && R < 64 && Cc >= 0 && Cc < 64)
            v = __half2float(g_img_h[(((size_t)((b << 6) + R) << 6) + Cc) * CH + ch0 + ch]);
        sin_[py][px][ch] = v;
    }
    __syncthreads();

    int ch = tid & 31, px = tid >> 5;
    float acc[8] = {};
    #pragma unroll
    for (int dx = 0; dx < 9; dx++) {
        float col[16];
        #pragma unroll
        for (int ry = 0; ry < 16; ry++) col[ry] = sin_[ry][px + dx][ch];
        #pragma unroll
        for (int dy = 0; dy < 9; dy++) {
            float wv = swt[dy * 9 + dx][ch];
            #pragma unroll
            for (int py = 0; py < 8; py++) acc[py] = fmaf(col[py + dy], wv, acc[py]);
        }
    }
    float bias = gb[ch0 + ch];
    #pragma unroll
    for (int py = 0; py < 8; py++) {
        int R = tr + py, Cc = tc + px;
        int wh = R & 7, ii = R >> 3, ww = Cc & 7, jj = Cc >> 3;
        int r = ((b * 64 + wh * 8 + ww) << 6) + (ii << 3) + jj;
        size_t o = (size_t)r * CH + ch0 + ch;
        g_att_h[o] = __float2half(__half2float(g_att_h[o]) + acc[py] + bias);
    }
}

// ---------------- host launch ----------------
extern "C" void kernel_launch(void* const* d_in, const int* in_sizes, int n_in,
                              void* d_out, int out_size) {
    int off = (n_in >= 18) ? 2 : 0;
    const float* x       = (const float*)d_in[off + 0];
    const float* norm1_g = (const float*)d_in[off + 1];
    const float* norm1_b = (const float*)d_in[off + 2];
    const float* qkv_w   = (const float*)d_in[off + 3];
    const float* qkv_b   = (const float*)d_in[off + 4];
    const float* rpb     = (const float*)d_in[off + 5];
    const float* proj_w  = (const float*)d_in[off + 6];
    const float* proj_b  = (const float*)d_in[off + 7];
    const float* gaze_w  = (const float*)d_in[off + 8];
    const float* gaze_b  = (const float*)d_in[off + 9];
    const float* norm2_g = (const float*)d_in[off + 10];
    const float* norm2_b = (const float*)d_in[off + 11];
    const float* fc1_w   = (const float*)d_in[off + 12];
    const float* fc1_b   = (const float*)d_in[off + 13];
    const float* fc2_w   = (const float*)d_in[off + 14];
    const float* fc2_b   = (const float*)d_in[off + 15];

    __half *pw_qkv, *pw_proj, *pw_fc1, *pw_fc2;
    __half *p_xnw, *p_atth, *p_ln2, *p_h1;
    cudaGetSymbolAddress((void**)&pw_qkv, w_qkv);
    cudaGetSymbolAddress((void**)&pw_proj, w_proj);
    cudaGetSymbolAddress((void**)&pw_fc1, w_fc1);
    cudaGetSymbolAddress((void**)&pw_fc2, w_fc2);
    cudaGetSymbolAddress((void**)&p_xnw, g_xnw_h);
    cudaGetSymbolAddress((void**)&p_atth, g_att_h);
    cudaGetSymbolAddress((void**)&p_ln2, g_ln2_h);
    cudaGetSymbolAddress((void**)&p_h1,  g_h1_h);

    cudaFuncSetAttribute((const void*)hgemm<EpiQKV>,  cudaFuncAttributeMaxDynamicSharedMemorySize, SMEM_DYN);
    cudaFuncSetAttribute((const void*)hgemm<EpiProj>, cudaFuncAttributeMaxDynamicSharedMemorySize, SMEM_DYN);
    cudaFuncSetAttribute((const void*)hgemm<EpiFC1>,  cudaFuncAttributeMaxDynamicSharedMemorySize, SMEM_DYN);
    cudaFuncSetAttribute((const void*)hgemm<EpiFC2>,  cudaFuncAttributeMaxDynamicSharedMemorySize, SMEM_DYN);

    cvt_all<<<768, 256>>>(qkv_w, proj_w, fc1_w, fc2_w);
    bias_kernel<<<128, 256>>>(rpb);
    ln1_kernel<<<2048, 256>>>(x, norm1_g, norm1_b);
    hgemm<EpiQKV><<<dim3(3, 512), 256, SMEM_DYN>>>(p_xnw, pw_qkv, 256, EpiQKV{qkv_b});
    attn_mma<<<8192, 128>>>();
    gaze_conv_kernel<<<8192, 256>>>(gaze_w, gaze_b);
    hgemm<EpiProj><<<dim3(1, 512), 256, SMEM_DYN>>>(p_atth, pw_proj, 256, EpiProj{proj_b});
    ln2_kernel<<<TOKENS, 256>>>(norm2_g, norm2_b);
    hgemm<EpiFC1><<<dim3(4, 512), 256, SMEM_DYN>>>(p_ln2, pw_fc1, 256, EpiFC1{fc1_b});
    hgemm<EpiFC2><<<dim3(1, 512), 256, SMEM_DYN>>>(p_h1, pw_fc2, 1024, EpiFC2{fc2_b, (float*)d_out});
}

// round 12
// speedup vs baseline: 1.1041x; 1.1041x over previous
#include <cuda_runtime.h>
#include <cuda_fp16.h>
#include <math.h>
#include <stdint.h>

#define BATCH   16
#define CH      256
#define TOKENS  (BATCH*64*64)      // 65536
#define HID     1024
#define NHEAD   8
#define NTOK    64

// ---------------- scratch (device globals; allocation-free) ----------------
__device__ float  g_xf  [TOKENS*CH];   // shortcut, token-major (fp32)
__device__ float  g_xf2 [TOKENS*CH];   // after proj residual, token-major (fp32)
__device__ float  g_bias[NHEAD*NTOK*NTOK];

__device__ __half g_xnw_h[TOKENS*CH];  // LN1 out, windowed
__device__ __half g_q   [TOKENS*CH];   // [win][head][pos][hd], pre-scaled
__device__ __half g_k   [TOKENS*CH];
__device__ __half g_v   [TOKENS*CH];
__device__ __half g_img_h[TOKENS*CH];  // folded image NHWC
__device__ __half g_att_h[TOKENS*CH];  // attn out; gaze accumulates in-place
__device__ __half g_ln2_h[TOKENS*CH];
__device__ __half g_h1_h [TOKENS*HID];

__device__ __half w_qkv [768*256];
__device__ __half w_proj[256*256];
__device__ __half w_fc1 [1024*256];
__device__ __half w_fc2 [256*1024];

// ============================ helpers ============================
__device__ __forceinline__ uint32_t smem_u32(const void* p) {
    uint32_t a;
    asm("{ .reg .u64 t; cvta.to.shared.u64 t, %1; cvt.u32.u64 %0, t; }" : "=r"(a) : "l"(p));
    return a;
}
__device__ __forceinline__ uint32_t f2h2(float a, float b) {
    __half2 h = __floats2half2_rn(a, b);
    return *reinterpret_cast<uint32_t*>(&h);
}
__device__ __forceinline__ void ldsm4(uint32_t (&r)[4], uint32_t addr) {
    asm volatile("ldmatrix.sync.aligned.m8n8.x4.shared.b16 {%0,%1,%2,%3}, [%4];"
                 : "=r"(r[0]), "=r"(r[1]), "=r"(r[2]), "=r"(r[3]) : "r"(addr));
}
__device__ __forceinline__ void ldsm4t(uint32_t (&r)[4], uint32_t addr) {
    asm volatile("ldmatrix.sync.aligned.m8n8.x4.trans.shared.b16 {%0,%1,%2,%3}, [%4];"
                 : "=r"(r[0]), "=r"(r[1]), "=r"(r[2]), "=r"(r[3]) : "r"(addr));
}
__device__ __forceinline__ void mma16816(float* d, const uint32_t* a, uint32_t b0, uint32_t b1) {
    asm volatile("mma.sync.aligned.m16n8k16.row.col.f32.f16.f16.f32 "
                 "{%0,%1,%2,%3},{%4,%5,%6,%7},{%8,%9},{%0,%1,%2,%3};"
                 : "+f"(d[0]), "+f"(d[1]), "+f"(d[2]), "+f"(d[3])
                 : "r"(a[0]), "r"(a[1]), "r"(a[2]), "r"(a[3]), "r"(b0), "r"(b1));
}
__device__ __forceinline__ void mma16816h(uint32_t* d, const uint32_t* a, uint32_t b0, uint32_t b1) {
    asm volatile("mma.sync.aligned.m16n8k16.row.col.f16.f16.f16.f16 "
                 "{%0,%1},{%2,%3,%4,%5},{%6,%7},{%0,%1};"
                 : "+r"(d[0]), "+r"(d[1])
                 : "r"(a[0]), "r"(a[1]), "r"(a[2]), "r"(a[3]), "r"(b0), "r"(b1));
}
#define CP_A16(dst, src) asm volatile("cp.async.cg.shared.global [%0], [%1], 16;" :: "r"(dst), "l"(src))
#define CP_COMMIT()      asm volatile("cp.async.commit_group;")
#define CP_WAIT(n)       asm volatile("cp.async.wait_group %0;" :: "n"(n))

// ============================ fp16 GEMM, cp.async 3-stage, f16 acc, BK=64 ============================
// C[m][n] = sum_k A[m][k]*W[n][k].  BM=BN=128, BK=64, 256 thr (2x4 warps), warp tile 64x32.
#define LDSTR 72                          // halves per smem row (144B stride, conflict-free)
#define SSZ   (128*LDSTR)                 // halves per tensor per stage
#define OFF_B (SSZ*2)                     // B offset within stage (bytes)
#define STG_B (2*SSZ*2)                   // bytes per stage (A+B) = 36864
#define SMEM_DYN (3*STG_B)                // 110592 bytes

template <class Epi>
__global__ __launch_bounds__(256, 2) void hgemm(const __half* __restrict__ A,
                                                const __half* __restrict__ W,
                                                int K, Epi epi) {
    extern __shared__ __half sm[];
    int tid = threadIdx.x, lane = tid & 31, wid = tid >> 5;
    int wm = wid >> 2, wn = wid & 3;
    int bm = blockIdx.y << 7, bn = blockIdx.x << 7;
    int NC = K >> 6;
    uint32_t smb = smem_u32(sm);

    auto issue = [&](int st, int ic) {
        int k0 = ic << 6;
        uint32_t sb = smb + st * STG_B;
        #pragma unroll
        for (int j = 0; j < 4; j++) {
            int ch = tid + (j << 8);
            int row = ch >> 3, cq = ch & 7;
            uint32_t da = sb + (row * LDSTR + cq * 8) * 2;
            CP_A16(da, A + (size_t)(bm + row) * K + k0 + cq * 8);
            CP_A16(da + OFF_B, W + (size_t)(bn + row) * K + k0 + cq * 8);
        }
        CP_COMMIT();
    };

    issue(0, 0);
    if (NC > 1) issue(1, 1);
    uint32_t acch[4][4][2] = {};
    for (int ic = 0; ic < NC; ic++) {
        if (ic + 1 < NC) CP_WAIT(1); else CP_WAIT(0);
        __syncthreads();
        if (ic + 2 < NC) issue((ic + 2) % 3, ic + 2);
        uint32_t baseA = smb + (ic % 3) * STG_B;
        uint32_t baseB = baseA + OFF_B;
        #pragma unroll
        for (int ks = 0; ks < 4; ks++) {
            uint32_t af[4][4], bf[2][4];
            #pragma unroll
            for (int mt = 0; mt < 4; mt++)
                ldsm4(af[mt], baseA + (((wm*64 + mt*16 + (lane & 15)) * LDSTR + ks*16 + (lane >> 4)*8) << 1));
            #pragma unroll
            for (int bt = 0; bt < 2; bt++)
                ldsm4(bf[bt], baseB + (((wn*32 + bt*16 + (lane & 15)) * LDSTR + ks*16 + (lane >> 4)*8) << 1));
            #pragma unroll
            for (int mt = 0; mt < 4; mt++)
                #pragma unroll
                for (int nt = 0; nt < 4; nt++)
                    mma16816h(acch[mt][nt], af[mt], bf[nt>>1][nt&1], bf[nt>>1][(nt&1)+2]);
        }
    }
    int g = lane >> 2, tg = lane & 3;

    if constexpr (Epi::STAGED) {
        // FC2: val = acc + bias + xf2, then NCHW-coalesced write via smem stage (2 half-tiles)
        float* stg = (float*)sm;
        int b = bm >> 12, hw0 = bm & 4095;
        for (int p = 0; p < 2; p++) {
            __syncthreads();
            if (wm == p) {
                #pragma unroll
                for (int mt = 0; mt < 4; mt++) {
                    int lr = mt * 16 + g;
                    size_t gr0 = (size_t)(bm + p * 64 + lr) * CH;
                    size_t gr1 = gr0 + 8 * CH;
                    #pragma unroll
                    for (int nt = 0; nt < 4; nt++) {
                        int c = wn * 32 + nt * 8 + tg * 2;
                        __half2 h0 = *(__half2*)&acch[mt][nt][0];
                        __half2 h1 = *(__half2*)&acch[mt][nt][1];
                        float2 x0 = *(const float2*)&g_xf2[gr0 + bn + c];
                        float2 x1 = *(const float2*)&g_xf2[gr1 + bn + c];
                        stg[lr * 132 + c]           = __low2float(h0)  + epi.bias[bn + c]     + x0.x;
                        stg[lr * 132 + c + 1]       = __high2float(h0) + epi.bias[bn + c + 1] + x0.y;
                        stg[(lr + 8) * 132 + c]     = __low2float(h1)  + epi.bias[bn + c]     + x1.x;
                        stg[(lr + 8) * 132 + c + 1] = __high2float(h1) + epi.bias[bn + c + 1] + x1.y;
                    }
                }
            }
            __syncthreads();
            #pragma unroll 1
            for (int i = 0; i < 32; i++) {
                int idx = tid + (i << 8);
                int row = idx & 63, c = idx >> 6;
                epi.out[((size_t)(b * CH + bn + c) << 12) + hw0 + p * 64 + row] = stg[row * 132 + c];
            }
        }
    } else {
        #pragma unroll
        for (int mt = 0; mt < 4; mt++) {
            int M0 = bm + wm * 64 + mt * 16;
            #pragma unroll
            for (int nt = 0; nt < 4; nt++) {
                int N0 = bn + wn * 32 + nt * 8 + tg * 2;
                __half2 h0 = *(__half2*)&acch[mt][nt][0];
                __half2 h1 = *(__half2*)&acch[mt][nt][1];
                epi.pair(M0 + g,     N0, __low2float(h0), __high2float(h0));
                epi.pair(M0 + g + 8, N0, __low2float(h1), __high2float(h1));
            }
        }
    }
}

// ============================ epilogues (pair interface: c even) ============================
struct EpiQKV {
    const float* bias;
    static constexpr bool STAGED = false;
    __device__ void pair(int r, int c, float a0, float a1) const {
        float va = a0 + bias[c], vb = a1 + bias[c + 1];
        int part = c >> 8, head = (c >> 5) & 7, d = c & 31;
        int win = r >> 6, pos = r & 63;
        size_t o = (size_t)(win * NHEAD + head) * 2048 + pos * 32 + d;
        if (part == 0)      *(uint32_t*)&g_q[o] = f2h2(va * 4.0f, vb * 4.0f);
        else if (part == 1) *(uint32_t*)&g_k[o] = f2h2(va, vb);
        else {
            uint32_t hv = f2h2(va, vb);
            *(uint32_t*)&g_v[o] = hv;
            int b = win >> 6, wh = (win >> 3) & 7, ww = win & 7;
            int ii = pos >> 3, jj = pos & 7;
            int R = ii * 8 + wh, Cc = jj * 8 + ww;
            *(uint32_t*)&g_img_h[(((size_t)((b << 6) + R) << 6) + Cc) * CH + (c - 512)] = hv;
        }
    }
};
struct EpiProj {
    const float* bias;
    static constexpr bool STAGED = false;
    __device__ void pair(int r, int c, float a0, float a1) const {
        int win = r >> 6, pos = r & 63;
        int b = win >> 6, wh = (win >> 3) & 7, ww = win & 7;
        int ii = pos >> 3, jj = pos & 7;
        int t = (b << 12) + ((wh * 8 + ii) << 6) + ww * 8 + jj;
        size_t o = (size_t)t * CH + c;
        float2 xf = *(const float2*)&g_xf[o];
        float2 res = make_float2(xf.x + a0 + bias[c], xf.y + a1 + bias[c + 1]);
        *(float2*)&g_xf2[o] = res;
    }
};
struct EpiFC1 {
    const float* bias;
    static constexpr bool STAGED = false;
    __device__ void pair(int r, int c, float a0, float a1) const {
        float x0 = a0 + bias[c], x1 = a1 + bias[c + 1];
        float g0 = 0.5f * x0 * (1.0f + erff(x0 * 0.70710678118654752f));
        float g1 = 0.5f * x1 * (1.0f + erff(x1 * 0.70710678118654752f));
        *(uint32_t*)&g_h1_h[(size_t)r * HID + c] = f2h2(g0, g1);
    }
};
struct EpiFC2 {
    const float* bias;
    float* out;
    static constexpr bool STAGED = true;
    __device__ void pair(int, int, float, float) const {}
};

// ---------------- all weights fp32 -> fp16, one vectorized launch ----------------
__global__ __launch_bounds__(256) void cvt_all(const float* __restrict__ qkv,
                                               const float* __restrict__ proj,
                                               const float* __restrict__ fc1,
                                               const float* __restrict__ fc2) {
    int i4 = blockIdx.x * 256 + threadIdx.x;    // 196608 float4 units
    int i = i4 * 4;
    const float* s;
    __half* d;
    if (i < 196608)      { s = qkv  + i;          d = w_qkv  + i; }
    else if (i < 262144) { s = proj + (i-196608); d = w_proj + (i-196608); }
    else if (i < 524288) { s = fc1  + (i-262144); d = w_fc1  + (i-262144); }
    else                 { s = fc2  + (i-524288); d = w_fc2  + (i-524288); }
    float4 v = *(const float4*)s;
    uint2 h;
    h.x = f2h2(v.x, v.y);
    h.y = f2h2(v.z, v.w);
    *(uint2*)d = h;
}

// ---------------- relative position bias prep ----------------
__global__ void bias_kernel(const float* __restrict__ rpb) {
    int idx = blockIdx.x * 256 + threadIdx.x;
    int h_ = idx >> 12, n = (idx >> 6) & 63, m = idx & 63;
    int di = (n >> 3) - (m >> 3) + 7;
    int dj = (n & 7) - (m & 7) + 7;
    g_bias[idx] = rpb[(di * 15 + dj) * NHEAD + h_];
}

// ---------------- LayerNorm 1 ----------------
__global__ __launch_bounds__(256) void ln1_kernel(const float* __restrict__ x,
                                                  const float* __restrict__ gw,
                                                  const float* __restrict__ gb) {
    __shared__ float tx[256][33];
    int t0 = blockIdx.x * 32;
    int b = t0 >> 12, hw0 = t0 & 4095;
    int tid = threadIdx.x;
    #pragma unroll
    for (int j = 0; j < 32; j++) {
        int idx = j * 256 + tid;
        int c = idx >> 5, i = idx & 31;
        tx[c][i] = x[((size_t)(b * CH + c) << 12) + hw0 + i];
    }
    __syncthreads();
    int lane = tid & 31, w = tid >> 5;
    #pragma unroll
    for (int q = 0; q < 4; q++) {
        int i = w * 4 + q;
        float s = 0.f, s2 = 0.f;
        #pragma unroll
        for (int k = 0; k < 8; k++) { float v = tx[lane + 32 * k][i]; s += v; s2 += v * v; }
        #pragma unroll
        for (int o = 16; o; o >>= 1) { s += __shfl_xor_sync(~0u, s, o); s2 += __shfl_xor_sync(~0u, s2, o); }
        float mean = s * (1.f / CH);
        float inv = rsqrtf(s2 * (1.f / CH) - mean * mean + 1e-5f);
        int t = t0 + i;
        int hw = hw0 + i, hh = hw >> 6, wc = hw & 63;
        int wh = hh >> 3, ii = hh & 7, ww = wc >> 3, jj = wc & 7;
        int r = ((b * 64 + wh * 8 + ww) << 6) + (ii << 3) + jj;
        #pragma unroll
        for (int k = 0; k < 8; k++) {
            int c = lane + 32 * k;
            float v = tx[c][i];
            g_xf[(size_t)t * CH + c] = v;
            g_xnw_h[(size_t)r * CH + c] = __float2half((v - mean) * inv * gw[c] + gb[c]);
        }
    }
}

// ---------------- LayerNorm 2: one warp per token, no block sync ----------------
__global__ __launch_bounds__(256) void ln2_kernel(const float* __restrict__ gw,
                                                  const float* __restrict__ gb) {
    int lane = threadIdx.x & 31, w = threadIdx.x >> 5;
    int t = blockIdx.x * 8 + w;
    const float* src = g_xf2 + (size_t)t * CH + lane * 8;
    float4 v0 = *(const float4*)src;
    float4 v1 = *(const float4*)(src + 4);
    float s  = v0.x + v0.y + v0.z + v0.w + v1.x + v1.y + v1.z + v1.w;
    float s2 = v0.x*v0.x + v0.y*v0.y + v0.z*v0.z + v0.w*v0.w
             + v1.x*v1.x + v1.y*v1.y + v1.z*v1.z + v1.w*v1.w;
    #pragma unroll
    for (int o = 16; o; o >>= 1) { s += __shfl_xor_sync(~0u, s, o); s2 += __shfl_xor_sync(~0u, s2, o); }
    float mean = s * (1.f / CH);
    float inv = rsqrtf(s2 * (1.f / CH) - mean * mean + 1e-5f);
    int c0 = lane * 8;
    float4 gwv0 = *(const float4*)(gw + c0), gwv1 = *(const float4*)(gw + c0 + 4);
    float4 gbv0 = *(const float4*)(gb + c0), gbv1 = *(const float4*)(gb + c0 + 4);
    uint4 outv;
    outv.x = f2h2((v0.x - mean) * inv * gwv0.x + gbv0.x, (v0.y - mean) * inv * gwv0.y + gbv0.y);
    outv.y = f2h2((v0.z - mean) * inv * gwv0.z + gbv0.z, (v0.w - mean) * inv * gwv0.w + gbv0.w);
    outv.z = f2h2((v1.x - mean) * inv * gwv1.x + gbv1.x, (v1.y - mean) * inv * gwv1.y + gbv1.y);
    outv.w = f2h2((v1.z - mean) * inv * gwv1.z + gbv1.z, (v1.w - mean) * inv * gwv1.w + gbv1.w);
    *(uint4*)(g_ln2_h + (size_t)t * CH + c0) = outv;
}

// ---------------- tensor-core attention: one block per (win, head), 4 warps ----------------
__global__ __launch_bounds__(128) void attn_mma() {
    int win = blockIdx.x >> 3, head = blockIdx.x & 7;
    __shared__ __half sq[64 * 40], sk[64 * 40], sv[64 * 40];
    __shared__ float sb[64 * 64];
    int tid = threadIdx.x, lane = tid & 31, w = tid >> 5;

    const __half* qb = g_q + (size_t)(win * NHEAD + head) * 2048;
    const __half* kb = g_k + (size_t)(win * NHEAD + head) * 2048;
    const __half* vb = g_v + (size_t)(win * NHEAD + head) * 2048;
    #pragma unroll
    for (int j = 0; j < 2; j++) {
        int ch = tid + (j << 7);
        int row = ch >> 2, cq = ch & 3;
        *(uint4*)&sq[row * 40 + cq * 8] = *(const uint4*)(qb + row * 32 + cq * 8);
        *(uint4*)&sk[row * 40 + cq * 8] = *(const uint4*)(kb + row * 32 + cq * 8);
        *(uint4*)&sv[row * 40 + cq * 8] = *(const uint4*)(vb + row * 32 + cq * 8);
    }
    const float4* bb = (const float4*)(g_bias + head * 4096);
    #pragma unroll
    for (int j = 0; j < 8; j++)
        ((float4*)sb)[tid + (j << 7)] = bb[tid + (j << 7)];
    __syncthreads();

    uint32_t bq = smem_u32(sq), bk = smem_u32(sk), bv = smem_u32(sv);
    int g = lane >> 2, tg = lane & 3;

    uint32_t aq[2][4];
    #pragma unroll
    for (int t = 0; t < 2; t++)
        ldsm4(aq[t], bq + (((16 * w + (lane & 15)) * 40 + t * 16 + (lane >> 4) * 8) << 1));

    float acc[8][4] = {};
    #pragma unroll
    for (int t = 0; t < 2; t++)
        #pragma unroll
        for (int u = 0; u < 4; u++) {
            uint32_t bf[4];
            ldsm4(bf, bk + (((16 * u + (lane & 15)) * 40 + t * 16 + (lane >> 4) * 8) << 1));
            mma16816(acc[2 * u],     aq[t], bf[0], bf[2]);
            mma16816(acc[2 * u + 1], aq[t], bf[1], bf[3]);
        }

    int r0 = 16 * w + g, r1 = r0 + 8;
    float mx0 = -1e30f, mx1 = -1e30f;
    #pragma unroll
    for (int s = 0; s < 8; s++) {
        acc[s][0] += sb[r0 * 64 + 8 * s + tg * 2];
        acc[s][1] += sb[r0 * 64 + 8 * s + tg * 2 + 1];
        acc[s][2] += sb[r1 * 64 + 8 * s + tg * 2];
        acc[s][3] += sb[r1 * 64 + 8 * s + tg * 2 + 1];
        mx0 = fmaxf(mx0, fmaxf(acc[s][0], acc[s][1]));
        mx1 = fmaxf(mx1, fmaxf(acc[s][2], acc[s][3]));
    }
    mx0 = fmaxf(mx0, __shfl_xor_sync(~0u, mx0, 1)); mx0 = fmaxf(mx0, __shfl_xor_sync(~0u, mx0, 2));
    mx1 = fmaxf(mx1, __shfl_xor_sync(~0u, mx1, 1)); mx1 = fmaxf(mx1, __shfl_xor_sync(~0u, mx1, 2));
    float sm0 = 0.f, sm1 = 0.f;
    #pragma unroll
    for (int s = 0; s < 8; s++) {
        acc[s][0] = __expf(acc[s][0] - mx0); acc[s][1] = __expf(acc[s][1] - mx0);
        acc[s][2] = __expf(acc[s][2] - mx1); acc[s][3] = __expf(acc[s][3] - mx1);
        sm0 += acc[s][0] + acc[s][1];
        sm1 += acc[s][2] + acc[s][3];
    }
    sm0 += __shfl_xor_sync(~0u, sm0, 1); sm0 += __shfl_xor_sync(~0u, sm0, 2);
    sm1 += __shfl_xor_sync(~0u, sm1, 1); sm1 += __shfl_xor_sync(~0u, sm1, 2);
    float iv0 = 1.f / sm0, iv1 = 1.f / sm1;
    uint32_t ap[4][4];
    #pragma unroll
    for (int t = 0; t < 4; t++) {
        ap[t][0] = f2h2(acc[2*t][0]*iv0,   acc[2*t][1]*iv0);
        ap[t][1] = f2h2(acc[2*t][2]*iv1,   acc[2*t][3]*iv1);
        ap[t][2] = f2h2(acc[2*t+1][0]*iv0, acc[2*t+1][1]*iv0);
        ap[t][3] = f2h2(acc[2*t+1][2]*iv1, acc[2*t+1][3]*iv1);
    }

    float oacc[4][4] = {};
    #pragma unroll
    for (int t = 0; t < 4; t++)
        #pragma unroll
        for (int np = 0; np < 2; np++) {
            uint32_t bf[4];
            ldsm4t(bf, bv + (((16 * t + (lane & 15)) * 40 + np * 16 + (lane >> 4) * 8) << 1));
            mma16816(oacc[2 * np],     ap[t], bf[0], bf[1]);
            mma16816(oacc[2 * np + 1], ap[t], bf[2], bf[3]);
        }

    __half* ob = g_att_h + ((size_t)win * 64) * 256 + head * 32;
    #pragma unroll
    for (int n = 0; n < 4; n++) {
        *(uint32_t*)&ob[(size_t)r0 * 256 + 8 * n + tg * 2] = f2h2(oacc[n][0], oacc[n][1]);
        *(uint32_t*)&ob[(size_t)r1 * 256 + 8 * n + tg * 2] = f2h2(oacc[n][2], oacc[n][3]);
    }
}

// ---------------- depthwise 9x9 conv + unfold; accumulates into g_att_h in place ----------------
__global__ __launch_bounds__(256) void gaze_conv_kernel(const float* __restrict__ gw,
                                                        const float* __restrict__ gb) {
    int bidx = blockIdx.x;                 // 16*64*8
    int cc = bidx & 7;
    int tile = (bidx >> 3) & 63;
    int b = bidx >> 9;
    int tr = (tile >> 3) << 3;
    int tc = (tile & 7) << 3;
    int ch0 = cc << 5;

    __shared__ float sin_[16][16][32];
    __shared__ float swt[81][32];
    int tid = threadIdx.x;

    for (int i = tid; i < 81 * 32; i += 256) {
        int tap = i >> 5, ch = i & 31;
        swt[tap][ch] = gw[tap * CH + ch0 + ch];
    }
    for (int i = tid; i < 16 * 16 * 32; i += 256) {
        int ch = i & 31, px = (i >> 5) & 15, py = i >> 9;
        int R = tr - 4 + py, Cc = tc - 4 + px;
        float v = 0.f;
        if (R >= 0 && R < 64 && Cc >= 0 && Cc < 64)
            v = __half2float(g_img_h[(((size_t)((b << 6) + R) << 6) + Cc) * CH + ch0 + ch]);
        sin_[py][px][ch] = v;
    }
    __syncthreads();

    int ch = tid & 31, px = tid >> 5;
    float acc[8] = {};
    #pragma unroll
    for (int dx = 0; dx < 9; dx++) {
        float col[16];
        #pragma unroll
        for (int ry = 0; ry < 16; ry++) col[ry] = sin_[ry][px + dx][ch];
        #pragma unroll
        for (int dy = 0; dy < 9; dy++) {
            float wv = swt[dy * 9 + dx][ch];
            #pragma unroll
            for (int py = 0; py < 8; py++) acc[py] = fmaf(col[py + dy], wv, acc[py]);
        }
    }
    float bias = gb[ch0 + ch];
    #pragma unroll
    for (int py = 0; py < 8; py++) {
        int R = tr + py, Cc = tc + px;
        int wh = R & 7, ii = R >> 3, ww = Cc & 7, jj = Cc >> 3;
        int r = ((b * 64 + wh * 8 + ww) << 6) + (ii << 3) + jj;
        size_t o = (size_t)r * CH + ch0 + ch;
        g_att_h[o] = __float2half(__half2float(g_att_h[o]) + acc[py] + bias);
    }
}

// ---------------- host launch ----------------
extern "C" void kernel_launch(void* const* d_in, const int* in_sizes, int n_in,
                              void* d_out, int out_size) {
    int off = (n_in >= 18) ? 2 : 0;
    const float* x       = (const float*)d_in[off + 0];
    const float* norm1_g = (const float*)d_in[off + 1];
    const float* norm1_b = (const float*)d_in[off + 2];
    const float* qkv_w   = (const float*)d_in[off + 3];
    const float* qkv_b   = (const float*)d_in[off + 4];
    const float* rpb     = (const float*)d_in[off + 5];
    const float* proj_w  = (const float*)d_in[off + 6];
    const float* proj_b  = (const float*)d_in[off + 7];
    const float* gaze_w  = (const float*)d_in[off + 8];
    const float* gaze_b  = (const float*)d_in[off + 9];
    const float* norm2_g = (const float*)d_in[off + 10];
    const float* norm2_b = (const float*)d_in[off + 11];
    const float* fc1_w   = (const float*)d_in[off + 12];
    const float* fc1_b   = (const float*)d_in[off + 13];
    const float* fc2_w   = (const float*)d_in[off + 14];
    const float* fc2_b   = (const float*)d_in[off + 15];

    __half *pw_qkv, *pw_proj, *pw_fc1, *pw_fc2;
    __half *p_xnw, *p_atth, *p_ln2, *p_h1;
    cudaGetSymbolAddress((void**)&pw_qkv, w_qkv);
    cudaGetSymbolAddress((void**)&pw_proj, w_proj);
    cudaGetSymbolAddress((void**)&pw_fc1, w_fc1);
    cudaGetSymbolAddress((void**)&pw_fc2, w_fc2);
    cudaGetSymbolAddress((void**)&p_xnw, g_xnw_h);
    cudaGetSymbolAddress((void**)&p_atth, g_att_h);
    cudaGetSymbolAddress((void**)&p_ln2, g_ln2_h);
    cudaGetSymbolAddress((void**)&p_h1,  g_h1_h);

    cudaFuncSetAttribute((const void*)hgemm<EpiQKV>,  cudaFuncAttributeMaxDynamicSharedMemorySize, SMEM_DYN);
    cudaFuncSetAttribute((const void*)hgemm<EpiProj>, cudaFuncAttributeMaxDynamicSharedMemorySize, SMEM_DYN);
    cudaFuncSetAttribute((const void*)hgemm<EpiFC1>,  cudaFuncAttributeMaxDynamicSharedMemorySize, SMEM_DYN);
    cudaFuncSetAttribute((const void*)hgemm<EpiFC2>,  cudaFuncAttributeMaxDynamicSharedMemorySize, SMEM_DYN);

    cvt_all<<<768, 256>>>(qkv_w, proj_w, fc1_w, fc2_w);
    bias_kernel<<<128, 256>>>(rpb);
    ln1_kernel<<<2048, 256>>>(x, norm1_g, norm1_b);
    hgemm<EpiQKV><<<dim3(6, 512), 256, SMEM_DYN>>>(p_xnw, pw_qkv, 256, EpiQKV{qkv_b});
    attn_mma<<<8192, 128>>>();
    gaze_conv_kernel<<<8192, 256>>>(gaze_w, gaze_b);
    hgemm<EpiProj><<<dim3(2, 512), 256, SMEM_DYN>>>(p_atth, pw_proj, 256, EpiProj{proj_b});
    ln2_kernel<<<8192, 256>>>(norm2_g, norm2_b);
    hgemm<EpiFC1><<<dim3(8, 512), 256, SMEM_DYN>>>(p_ln2, pw_fc1, 256, EpiFC1{fc1_b});
    hgemm<EpiFC2><<<dim3(2, 512), 256, SMEM_DYN>>>(p_h1, pw_fc2, 1024, EpiFC2{fc2_b, (float*)d_out});
}

// round 13
// speedup vs baseline: 1.1259x; 1.0198x over previous
#include <cuda_runtime.h>
#include <cuda_fp16.h>
#include <math.h>
#include <stdint.h>

#define BATCH   16
#define CH      256
#define TOKENS  (BATCH*64*64)      // 65536
#define HID     1024
#define NHEAD   8
#define NTOK    64

// ---------------- scratch (device globals; allocation-free) ----------------
__device__ float  g_xf  [TOKENS*CH];   // shortcut, token-major (fp32)
__device__ float  g_xf2 [TOKENS*CH];   // after proj residual, token-major (fp32)
__device__ float  g_bias[NHEAD*NTOK*NTOK];

__device__ __half g_xnw_h[TOKENS*CH];  // LN1 out, windowed
__device__ __half g_q   [TOKENS*CH];   // [win][head][pos][hd], pre-scaled
__device__ __half g_k   [TOKENS*CH];
__device__ __half g_v   [TOKENS*CH];
__device__ __half g_img_h[TOKENS*CH];  // folded image NHWC
__device__ __half g_att_h[TOKENS*CH];  // attn out; gaze accumulates in-place
__device__ __half g_ln2_h[TOKENS*CH];
__device__ __half g_h1_h [TOKENS*HID];

__device__ __half w_qkv [768*256];
__device__ __half w_proj[256*256];
__device__ __half w_fc1 [1024*256];
__device__ __half w_fc2 [256*1024];

// ============================ helpers ============================
__device__ __forceinline__ uint32_t smem_u32(const void* p) {
    uint32_t a;
    asm("{ .reg .u64 t; cvta.to.shared.u64 t, %1; cvt.u32.u64 %0, t; }" : "=r"(a) : "l"(p));
    return a;
}
__device__ __forceinline__ uint32_t f2h2(float a, float b) {
    __half2 h = __floats2half2_rn(a, b);
    return *reinterpret_cast<uint32_t*>(&h);
}
__device__ __forceinline__ void ldsm4(uint32_t (&r)[4], uint32_t addr) {
    asm volatile("ldmatrix.sync.aligned.m8n8.x4.shared.b16 {%0,%1,%2,%3}, [%4];"
                 : "=r"(r[0]), "=r"(r[1]), "=r"(r[2]), "=r"(r[3]) : "r"(addr));
}
__device__ __forceinline__ void ldsm4t(uint32_t (&r)[4], uint32_t addr) {
    asm volatile("ldmatrix.sync.aligned.m8n8.x4.trans.shared.b16 {%0,%1,%2,%3}, [%4];"
                 : "=r"(r[0]), "=r"(r[1]), "=r"(r[2]), "=r"(r[3]) : "r"(addr));
}
__device__ __forceinline__ void mma16816(float* d, const uint32_t* a, uint32_t b0, uint32_t b1) {
    asm volatile("mma.sync.aligned.m16n8k16.row.col.f32.f16.f16.f32 "
                 "{%0,%1,%2,%3},{%4,%5,%6,%7},{%8,%9},{%0,%1,%2,%3};"
                 : "+f"(d[0]), "+f"(d[1]), "+f"(d[2]), "+f"(d[3])
                 : "r"(a[0]), "r"(a[1]), "r"(a[2]), "r"(a[3]), "r"(b0), "r"(b1));
}
__device__ __forceinline__ void mma16816h(uint32_t* d, const uint32_t* a, uint32_t b0, uint32_t b1) {
    asm volatile("mma.sync.aligned.m16n8k16.row.col.f16.f16.f16.f16 "
                 "{%0,%1},{%2,%3,%4,%5},{%6,%7},{%0,%1};"
                 : "+r"(d[0]), "+r"(d[1])
                 : "r"(a[0]), "r"(a[1]), "r"(a[2]), "r"(a[3]), "r"(b0), "r"(b1));
}
#define CP_A16(dst, src) asm volatile("cp.async.cg.shared.global [%0], [%1], 16;" :: "r"(dst), "l"(src))
#define CP_COMMIT()      asm volatile("cp.async.commit_group;")
#define CP_WAIT(n)       asm volatile("cp.async.wait_group %0;" :: "n"(n))

// ============================ fp16 GEMM, cp.async 3-stage, f16 accumulators ============================
// C[m][n] = sum_k A[m][k]*W[n][k].  BM=BN=128, BK=32, 256 thr (2x4 warps), warp tile 64x32.
#define LDSTR 40
#define SSZ   (128*LDSTR)                 // halves per tensor per stage
#define SMEM_DYN (3*2*SSZ*2)              // 61440 bytes

template <class Epi>
__global__ __launch_bounds__(256, 2) void hgemm(const __half* __restrict__ A,
                                                const __half* __restrict__ W,
                                                int K, Epi epi) {
    extern __shared__ __half sm[];
    int tid = threadIdx.x, lane = tid & 31, wid = tid >> 5;
    int wm = wid >> 2, wn = wid & 3;
    int bm = blockIdx.y << 7, bn = blockIdx.x << 7;
    int NC = K >> 5;
    uint32_t smb = smem_u32(sm);

    auto issue = [&](int st, int ic) {
        int k0 = ic << 5;
        uint32_t sb = smb + st * (2 * SSZ) * 2;
        #pragma unroll
        for (int j = 0; j < 2; j++) {
            int ch = tid + (j << 8);
            int row = ch >> 2, cq = ch & 3;
            uint32_t da = sb + (row * LDSTR + cq * 8) * 2;
            CP_A16(da, A + (size_t)(bm + row) * K + k0 + cq * 8);
            CP_A16(da + SSZ * 2, W + (size_t)(bn + row) * K + k0 + cq * 8);
        }
        CP_COMMIT();
    };

    issue(0, 0); issue(1, 1);
    uint32_t acch[4][4][2] = {};
    for (int ic = 0; ic < NC; ic++) {
        if (ic + 1 < NC) CP_WAIT(1); else CP_WAIT(0);
        __syncthreads();
        if (ic + 2 < NC) issue((ic + 2) % 3, ic + 2);
        uint32_t baseA = smb + (ic % 3) * (2 * SSZ) * 2;
        uint32_t baseB = baseA + SSZ * 2;
        #pragma unroll
        for (int ks = 0; ks < 2; ks++) {
            uint32_t af[4][4], bf[2][4];
            #pragma unroll
            for (int mt = 0; mt < 4; mt++)
                ldsm4(af[mt], baseA + (((wm*64 + mt*16 + (lane & 15)) * LDSTR + ks*16 + (lane >> 4)*8) << 1));
            #pragma unroll
            for (int bt = 0; bt < 2; bt++)
                ldsm4(bf[bt], baseB + (((wn*32 + bt*16 + (lane & 15)) * LDSTR + ks*16 + (lane >> 4)*8) << 1));
            #pragma unroll
            for (int mt = 0; mt < 4; mt++)
                #pragma unroll
                for (int nt = 0; nt < 4; nt++)
                    mma16816h(acch[mt][nt], af[mt], bf[nt>>1][nt&1], bf[nt>>1][(nt&1)+2]);
        }
    }
    int g = lane >> 2, tg = lane & 3;

    if constexpr (Epi::STAGED) {
        // FC2: val = acc + bias + xf2, then NCHW-coalesced write via smem stage (2 half-tiles)
        float* stg = (float*)sm;
        int b = bm >> 12, hw0 = bm & 4095;
        for (int p = 0; p < 2; p++) {
            __syncthreads();
            if (wm == p) {
                #pragma unroll
                for (int mt = 0; mt < 4; mt++) {
                    int lr = mt * 16 + g;
                    size_t gr0 = (size_t)(bm + p * 64 + lr) * CH;
                    size_t gr1 = gr0 + 8 * CH;
                    #pragma unroll
                    for (int nt = 0; nt < 4; nt++) {
                        int c = wn * 32 + nt * 8 + tg * 2;
                        __half2 h0 = *(__half2*)&acch[mt][nt][0];
                        __half2 h1 = *(__half2*)&acch[mt][nt][1];
                        float2 x0 = *(const float2*)&g_xf2[gr0 + bn + c];
                        float2 x1 = *(const float2*)&g_xf2[gr1 + bn + c];
                        stg[lr * 132 + c]           = __low2float(h0)  + epi.bias[bn + c]     + x0.x;
                        stg[lr * 132 + c + 1]       = __high2float(h0) + epi.bias[bn + c + 1] + x0.y;
                        stg[(lr + 8) * 132 + c]     = __low2float(h1)  + epi.bias[bn + c]     + x1.x;
                        stg[(lr + 8) * 132 + c + 1] = __high2float(h1) + epi.bias[bn + c + 1] + x1.y;
                    }
                }
            }
            __syncthreads();
            #pragma unroll 1
            for (int i = 0; i < 32; i++) {
                int idx = tid + (i << 8);
                int row = idx & 63, c = idx >> 6;
                epi.out[((size_t)(b * CH + bn + c) << 12) + hw0 + p * 64 + row] = stg[row * 132 + c];
            }
        }
    } else {
        #pragma unroll
        for (int mt = 0; mt < 4; mt++) {
            int M0 = bm + wm * 64 + mt * 16;
            #pragma unroll
            for (int nt = 0; nt < 4; nt++) {
                int N0 = bn + wn * 32 + nt * 8 + tg * 2;
                __half2 h0 = *(__half2*)&acch[mt][nt][0];
                __half2 h1 = *(__half2*)&acch[mt][nt][1];
                epi.pair(M0 + g,     N0, __low2float(h0), __high2float(h0));
                epi.pair(M0 + g + 8, N0, __low2float(h1), __high2float(h1));
            }
        }
    }
}

// ============================ epilogues (pair interface: c even) ============================
struct EpiQKV {
    const float* bias;
    static constexpr bool STAGED = false;
    __device__ void pair(int r, int c, float a0, float a1) const {
        float va = a0 + bias[c], vb = a1 + bias[c + 1];
        int part = c >> 8, head = (c >> 5) & 7, d = c & 31;
        int win = r >> 6, pos = r & 63;
        size_t o = (size_t)(win * NHEAD + head) * 2048 + pos * 32 + d;
        if (part == 0)      *(uint32_t*)&g_q[o] = f2h2(va * 4.0f, vb * 4.0f);
        else if (part == 1) *(uint32_t*)&g_k[o] = f2h2(va, vb);
        else {
            uint32_t hv = f2h2(va, vb);
            *(uint32_t*)&g_v[o] = hv;
            int b = win >> 6, wh = (win >> 3) & 7, ww = win & 7;
            int ii = pos >> 3, jj = pos & 7;
            int R = ii * 8 + wh, Cc = jj * 8 + ww;
            *(uint32_t*)&g_img_h[(((size_t)((b << 6) + R) << 6) + Cc) * CH + (c - 512)] = hv;
        }
    }
};
struct EpiProj {
    const float* bias;
    static constexpr bool STAGED = false;
    __device__ void pair(int r, int c, float a0, float a1) const {
        int win = r >> 6, pos = r & 63;
        int b = win >> 6, wh = (win >> 3) & 7, ww = win & 7;
        int ii = pos >> 3, jj = pos & 7;
        int t = (b << 12) + ((wh * 8 + ii) << 6) + ww * 8 + jj;
        size_t o = (size_t)t * CH + c;
        float2 xf = *(const float2*)&g_xf[o];
        float2 res = make_float2(xf.x + a0 + bias[c], xf.y + a1 + bias[c + 1]);
        *(float2*)&g_xf2[o] = res;
    }
};
struct EpiFC1 {
    const float* bias;
    static constexpr bool STAGED = false;
    __device__ void pair(int r, int c, float a0, float a1) const {
        float x0 = a0 + bias[c], x1 = a1 + bias[c + 1];
        float g0 = 0.5f * x0 * (1.0f + erff(x0 * 0.70710678118654752f));
        float g1 = 0.5f * x1 * (1.0f + erff(x1 * 0.70710678118654752f));
        *(uint32_t*)&g_h1_h[(size_t)r * HID + c] = f2h2(g0, g1);
    }
};
struct EpiFC2 {
    const float* bias;
    float* out;
    static constexpr bool STAGED = true;
    __device__ void pair(int, int, float, float) const {}
};

// ---------------- all weights fp32 -> fp16, one vectorized launch ----------------
__global__ __launch_bounds__(256) void cvt_all(const float* __restrict__ qkv,
                                               const float* __restrict__ proj,
                                               const float* __restrict__ fc1,
                                               const float* __restrict__ fc2) {
    int i4 = blockIdx.x * 256 + threadIdx.x;    // 196608 float4 units
    int i = i4 * 4;
    const float* s;
    __half* d;
    if (i < 196608)      { s = qkv  + i;          d = w_qkv  + i; }
    else if (i < 262144) { s = proj + (i-196608); d = w_proj + (i-196608); }
    else if (i < 524288) { s = fc1  + (i-262144); d = w_fc1  + (i-262144); }
    else                 { s = fc2  + (i-524288); d = w_fc2  + (i-524288); }
    float4 v = *(const float4*)s;
    uint2 h;
    h.x = f2h2(v.x, v.y);
    h.y = f2h2(v.z, v.w);
    *(uint2*)d = h;
}

// ---------------- relative position bias prep ----------------
__global__ void bias_kernel(const float* __restrict__ rpb) {
    int idx = blockIdx.x * 256 + threadIdx.x;
    int h_ = idx >> 12, n = (idx >> 6) & 63, m = idx & 63;
    int di = (n >> 3) - (m >> 3) + 7;
    int dj = (n & 7) - (m & 7) + 7;
    g_bias[idx] = rpb[(di * 15 + dj) * NHEAD + h_];
}

// ---------------- LayerNorm 1 ----------------
__global__ __launch_bounds__(256) void ln1_kernel(const float* __restrict__ x,
                                                  const float* __restrict__ gw,
                                                  const float* __restrict__ gb) {
    __shared__ float tx[256][33];
    int t0 = blockIdx.x * 32;
    int b = t0 >> 12, hw0 = t0 & 4095;
    int tid = threadIdx.x;
    #pragma unroll
    for (int j = 0; j < 32; j++) {
        int idx = j * 256 + tid;
        int c = idx >> 5, i = idx & 31;
        tx[c][i] = x[((size_t)(b * CH + c) << 12) + hw0 + i];
    }
    __syncthreads();
    int lane = tid & 31, w = tid >> 5;
    #pragma unroll
    for (int q = 0; q < 4; q++) {
        int i = w * 4 + q;
        float s = 0.f, s2 = 0.f;
        #pragma unroll
        for (int k = 0; k < 8; k++) { float v = tx[lane + 32 * k][i]; s += v; s2 += v * v; }
        #pragma unroll
        for (int o = 16; o; o >>= 1) { s += __shfl_xor_sync(~0u, s, o); s2 += __shfl_xor_sync(~0u, s2, o); }
        float mean = s * (1.f / CH);
        float inv = rsqrtf(s2 * (1.f / CH) - mean * mean + 1e-5f);
        int t = t0 + i;
        int hw = hw0 + i, hh = hw >> 6, wc = hw & 63;
        int wh = hh >> 3, ii = hh & 7, ww = wc >> 3, jj = wc & 7;
        int r = ((b * 64 + wh * 8 + ww) << 6) + (ii << 3) + jj;
        #pragma unroll
        for (int k = 0; k < 8; k++) {
            int c = lane + 32 * k;
            float v = tx[c][i];
            g_xf[(size_t)t * CH + c] = v;
            g_xnw_h[(size_t)r * CH + c] = __float2half((v - mean) * inv * gw[c] + gb[c]);
        }
    }
}

// ---------------- LayerNorm 2: one warp per token, no block sync ----------------
__global__ __launch_bounds__(256) void ln2_kernel(const float* __restrict__ gw,
                                                  const float* __restrict__ gb) {
    int lane = threadIdx.x & 31, w = threadIdx.x >> 5;
    int t = blockIdx.x * 8 + w;
    const float* src = g_xf2 + (size_t)t * CH + lane * 8;
    float4 v0 = *(const float4*)src;
    float4 v1 = *(const float4*)(src + 4);
    float s  = v0.x + v0.y + v0.z + v0.w + v1.x + v1.y + v1.z + v1.w;
    float s2 = v0.x*v0.x + v0.y*v0.y + v0.z*v0.z + v0.w*v0.w
             + v1.x*v1.x + v1.y*v1.y + v1.z*v1.z + v1.w*v1.w;
    #pragma unroll
    for (int o = 16; o; o >>= 1) { s += __shfl_xor_sync(~0u, s, o); s2 += __shfl_xor_sync(~0u, s2, o); }
    float mean = s * (1.f / CH);
    float inv = rsqrtf(s2 * (1.f / CH) - mean * mean + 1e-5f);
    int c0 = lane * 8;
    float4 gwv0 = *(const float4*)(gw + c0), gwv1 = *(const float4*)(gw + c0 + 4);
    float4 gbv0 = *(const float4*)(gb + c0), gbv1 = *(const float4*)(gb + c0 + 4);
    uint4 outv;
    outv.x = f2h2((v0.x - mean) * inv * gwv0.x + gbv0.x, (v0.y - mean) * inv * gwv0.y + gbv0.y);
    outv.y = f2h2((v0.z - mean) * inv * gwv0.z + gbv0.z, (v0.w - mean) * inv * gwv0.w + gbv0.w);
    outv.z = f2h2((v1.x - mean) * inv * gwv1.x + gbv1.x, (v1.y - mean) * inv * gwv1.y + gbv1.y);
    outv.w = f2h2((v1.z - mean) * inv * gwv1.z + gbv1.z, (v1.w - mean) * inv * gwv1.w + gbv1.w);
    *(uint4*)(g_ln2_h + (size_t)t * CH + c0) = outv;
}

// ---------------- tensor-core attention: one block per (win, head), 4 warps ----------------
__global__ __launch_bounds__(128) void attn_mma() {
    int win = blockIdx.x >> 3, head = blockIdx.x & 7;
    __shared__ __half sq[64 * 40], sk[64 * 40], sv[64 * 40];
    __shared__ float sb[64 * 64];
    int tid = threadIdx.x, lane = tid & 31, w = tid >> 5;

    const __half* qb = g_q + (size_t)(win * NHEAD + head) * 2048;
    const __half* kb = g_k + (size_t)(win * NHEAD + head) * 2048;
    const __half* vb = g_v + (size_t)(win * NHEAD + head) * 2048;
    #pragma unroll
    for (int j = 0; j < 2; j++) {
        int ch = tid + (j << 7);
        int row = ch >> 2, cq = ch & 3;
        *(uint4*)&sq[row * 40 + cq * 8] = *(const uint4*)(qb + row * 32 + cq * 8);
        *(uint4*)&sk[row * 40 + cq * 8] = *(const uint4*)(kb + row * 32 + cq * 8);
        *(uint4*)&sv[row * 40 + cq * 8] = *(const uint4*)(vb + row * 32 + cq * 8);
    }
    const float4* bb = (const float4*)(g_bias + head * 4096);
    #pragma unroll
    for (int j = 0; j < 8; j++)
        ((float4*)sb)[tid + (j << 7)] = bb[tid + (j << 7)];
    __syncthreads();

    uint32_t bq = smem_u32(sq), bk = smem_u32(sk), bv = smem_u32(sv);
    int g = lane >> 2, tg = lane & 3;

    uint32_t aq[2][4];
    #pragma unroll
    for (int t = 0; t < 2; t++)
        ldsm4(aq[t], bq + (((16 * w + (lane & 15)) * 40 + t * 16 + (lane >> 4) * 8) << 1));

    float acc[8][4] = {};
    #pragma unroll
    for (int t = 0; t < 2; t++)
        #pragma unroll
        for (int u = 0; u < 4; u++) {
            uint32_t bf[4];
            ldsm4(bf, bk + (((16 * u + (lane & 15)) * 40 + t * 16 + (lane >> 4) * 8) << 1));
            mma16816(acc[2 * u],     aq[t], bf[0], bf[2]);
            mma16816(acc[2 * u + 1], aq[t], bf[1], bf[3]);
        }

    int r0 = 16 * w + g, r1 = r0 + 8;
    float mx0 = -1e30f, mx1 = -1e30f;
    #pragma unroll
    for (int s = 0; s < 8; s++) {
        acc[s][0] += sb[r0 * 64 + 8 * s + tg * 2];
        acc[s][1] += sb[r0 * 64 + 8 * s + tg * 2 + 1];
        acc[s][2] += sb[r1 * 64 + 8 * s + tg * 2];
        acc[s][3] += sb[r1 * 64 + 8 * s + tg * 2 + 1];
        mx0 = fmaxf(mx0, fmaxf(acc[s][0], acc[s][1]));
        mx1 = fmaxf(mx1, fmaxf(acc[s][2], acc[s][3]));
    }
    mx0 = fmaxf(mx0, __shfl_xor_sync(~0u, mx0, 1)); mx0 = fmaxf(mx0, __shfl_xor_sync(~0u, mx0, 2));
    mx1 = fmaxf(mx1, __shfl_xor_sync(~0u, mx1, 1)); mx1 = fmaxf(mx1, __shfl_xor_sync(~0u, mx1, 2));
    float sm0 = 0.f, sm1 = 0.f;
    #pragma unroll
    for (int s = 0; s < 8; s++) {
        acc[s][0] = __expf(acc[s][0] - mx0); acc[s][1] = __expf(acc[s][1] - mx0);
        acc[s][2] = __expf(acc[s][2] - mx1); acc[s][3] = __expf(acc[s][3] - mx1);
        sm0 += acc[s][0] + acc[s][1];
        sm1 += acc[s][2] + acc[s][3];
    }
    sm0 += __shfl_xor_sync(~0u, sm0, 1); sm0 += __shfl_xor_sync(~0u, sm0, 2);
    sm1 += __shfl_xor_sync(~0u, sm1, 1); sm1 += __shfl_xor_sync(~0u, sm1, 2);
    float iv0 = 1.f / sm0, iv1 = 1.f / sm1;
    uint32_t ap[4][4];
    #pragma unroll
    for (int t = 0; t < 4; t++) {
        ap[t][0] = f2h2(acc[2*t][0]*iv0,   acc[2*t][1]*iv0);
        ap[t][1] = f2h2(acc[2*t][2]*iv1,   acc[2*t][3]*iv1);
        ap[t][2] = f2h2(acc[2*t+1][0]*iv0, acc[2*t+1][1]*iv0);
        ap[t][3] = f2h2(acc[2*t+1][2]*iv1, acc[2*t+1][3]*iv1);
    }

    float oacc[4][4] = {};
    #pragma unroll
    for (int t = 0; t < 4; t++)
        #pragma unroll
        for (int np = 0; np < 2; np++) {
            uint32_t bf[4];
            ldsm4t(bf, bv + (((16 * t + (lane & 15)) * 40 + np * 16 + (lane >> 4) * 8) << 1));
            mma16816(oacc[2 * np],     ap[t], bf[0], bf[1]);
            mma16816(oacc[2 * np + 1], ap[t], bf[2], bf[3]);
        }

    __half* ob = g_att_h + ((size_t)win * 64) * 256 + head * 32;
    #pragma unroll
    for (int n = 0; n < 4; n++) {
        *(uint32_t*)&ob[(size_t)r0 * 256 + 8 * n + tg * 2] = f2h2(oacc[n][0], oacc[n][1]);
        *(uint32_t*)&ob[(size_t)r1 * 256 + 8 * n + tg * 2] = f2h2(oacc[n][2], oacc[n][3]);
    }
}

// ---------------- depthwise 9x9 conv + unfold; accumulates into g_att_h in place ----------------
__global__ __launch_bounds__(256) void gaze_conv_kernel(const float* __restrict__ gw,
                                                        const float* __restrict__ gb) {
    int bidx = blockIdx.x;                 // 16*64*8
    int cc = bidx & 7;
    int tile = (bidx >> 3) & 63;
    int b = bidx >> 9;
    int tr = (tile >> 3) << 3;
    int tc = (tile & 7) << 3;
    int ch0 = cc << 5;

    __shared__ float sin_[16][16][32];
    __shared__ float swt[81][32];
    int tid = threadIdx.x;

    for (int i = tid; i < 81 * 32; i += 256) {
        int tap = i >> 5, ch = i & 31;
        swt[tap][ch] = gw[tap * CH + ch0 + ch];
    }
    for (int i = tid; i < 16 * 16 * 32; i += 256) {
        int ch = i & 31, px = (i >> 5) & 15, py = i >> 9;
        int R = tr - 4 + py, Cc = tc - 4 + px;
        float v = 0.f;
        if (R >= 0 && R < 64 && Cc >= 0 && Cc < 64)
            v = __half2float(g_img_h[(((size_t)((b << 6) + R) << 6) + Cc) * CH + ch0 + ch]);
        sin_[py][px][ch] = v;
    }
    __syncthreads();

    int ch = tid & 31, px = tid >> 5;
    float acc[8] = {};
    #pragma unroll
    for (int dx = 0; dx < 9; dx++) {
        float col[16];
        #pragma unroll
        for (int ry = 0; ry < 16; ry++) col[ry] = sin_[ry][px + dx][ch];
        #pragma unroll
        for (int dy = 0; dy < 9; dy++) {
            float wv = swt[dy * 9 + dx][ch];
            #pragma unroll
            for (int py = 0; py < 8; py++) acc[py] = fmaf(col[py + dy], wv, acc[py]);
        }
    }
    float bias = gb[ch0 + ch];
    #pragma unroll
    for (int py = 0; py < 8; py++) {
        int R = tr + py, Cc = tc + px;
        int wh = R & 7, ii = R >> 3, ww = Cc & 7, jj = Cc >> 3;
        int r = ((b * 64 + wh * 8 + ww) << 6) + (ii << 3) + jj;
        size_t o = (size_t)r * CH + ch0 + ch;
        g_att_h[o] = __float2half(__half2float(g_att_h[o]) + acc[py] + bias);
    }
}

// ---------------- host launch ----------------
extern "C" void kernel_launch(void* const* d_in, const int* in_sizes, int n_in,
                              void* d_out, int out_size) {
    int off = (n_in >= 18) ? 2 : 0;
    const float* x       = (const float*)d_in[off + 0];
    const float* norm1_g = (const float*)d_in[off + 1];
    const float* norm1_b = (const float*)d_in[off + 2];
    const float* qkv_w   = (const float*)d_in[off + 3];
    const float* qkv_b   = (const float*)d_in[off + 4];
    const float* rpb     = (const float*)d_in[off + 5];
    const float* proj_w  = (const float*)d_in[off + 6];
    const float* proj_b  = (const float*)d_in[off + 7];
    const float* gaze_w  = (const float*)d_in[off + 8];
    const float* gaze_b  = (const float*)d_in[off + 9];
    const float* norm2_g = (const float*)d_in[off + 10];
    const float* norm2_b = (const float*)d_in[off + 11];
    const float* fc1_w   = (const float*)d_in[off + 12];
    const float* fc1_b   = (const float*)d_in[off + 13];
    const float* fc2_w   = (const float*)d_in[off + 14];
    const float* fc2_b   = (const float*)d_in[off + 15];

    __half *pw_qkv, *pw_proj, *pw_fc1, *pw_fc2;
    __half *p_xnw, *p_atth, *p_ln2, *p_h1;
    cudaGetSymbolAddress((void**)&pw_qkv, w_qkv);
    cudaGetSymbolAddress((void**)&pw_proj, w_proj);
    cudaGetSymbolAddress((void**)&pw_fc1, w_fc1);
    cudaGetSymbolAddress((void**)&pw_fc2, w_fc2);
    cudaGetSymbolAddress((void**)&p_xnw, g_xnw_h);
    cudaGetSymbolAddress((void**)&p_atth, g_att_h);
    cudaGetSymbolAddress((void**)&p_ln2, g_ln2_h);
    cudaGetSymbolAddress((void**)&p_h1,  g_h1_h);

    cudaFuncSetAttribute((const void*)hgemm<EpiQKV>,  cudaFuncAttributeMaxDynamicSharedMemorySize, SMEM_DYN);
    cudaFuncSetAttribute((const void*)hgemm<EpiProj>, cudaFuncAttributeMaxDynamicSharedMemorySize, SMEM_DYN);
    cudaFuncSetAttribute((const void*)hgemm<EpiFC1>,  cudaFuncAttributeMaxDynamicSharedMemorySize, SMEM_DYN);
    cudaFuncSetAttribute((const void*)hgemm<EpiFC2>,  cudaFuncAttributeMaxDynamicSharedMemorySize, SMEM_DYN);

    cvt_all<<<768, 256>>>(qkv_w, proj_w, fc1_w, fc2_w);
    bias_kernel<<<128, 256>>>(rpb);
    ln1_kernel<<<2048, 256>>>(x, norm1_g, norm1_b);
    hgemm<EpiQKV><<<dim3(6, 512), 256, SMEM_DYN>>>(p_xnw, pw_qkv, 256, EpiQKV{qkv_b});
    attn_mma<<<8192, 128>>>();
    gaze_conv_kernel<<<8192, 256>>>(gaze_w, gaze_b);
    hgemm<EpiProj><<<dim3(2, 512), 256, SMEM_DYN>>>(p_atth, pw_proj, 256, EpiProj{proj_b});
    ln2_kernel<<<8192, 256>>>(norm2_g, norm2_b);
    hgemm<EpiFC1><<<dim3(8, 512), 256, SMEM_DYN>>>(p_ln2, pw_fc1, 256, EpiFC1{fc1_b});
    hgemm<EpiFC2><<<dim3(2, 512), 256, SMEM_DYN>>>(p_h1, pw_fc2, 1024, EpiFC2{fc2_b, (float*)d_out});
}

// round 14
// speedup vs baseline: 1.2308x; 1.0931x over previous
#include <cuda_runtime.h>
#include <cuda_fp16.h>
#include <math.h>
#include <stdint.h>

#define BATCH   16
#define CH      256
#define TOKENS  (BATCH*64*64)      // 65536
#define HID     1024
#define NHEAD   8
#define NTOK    64

// ---------------- scratch (device globals; allocation-free) ----------------
__device__ float  g_xf  [TOKENS*CH];   // shortcut, token-major (fp32)
__device__ float  g_xf2 [TOKENS*CH];   // after proj residual, token-major (fp32)
__device__ float  g_bias[NHEAD*NTOK*NTOK];

__device__ __half g_xnw_h[TOKENS*CH];  // LN1 out, windowed
__device__ __half g_q   [TOKENS*CH];   // [win][head][pos][hd], pre-scaled
__device__ __half g_k   [TOKENS*CH];
__device__ __half g_v   [TOKENS*CH];
__device__ __half g_img_h[TOKENS*CH];  // folded image NHWC
__device__ __half g_att_h[TOKENS*CH];  // attn out; gaze accumulates in-place
__device__ __half g_ln2_h[TOKENS*CH];
__device__ __half g_h1_h [TOKENS*HID];

__device__ __half w_qkv [768*256];
__device__ __half w_proj[256*256];
__device__ __half w_fc1 [1024*256];
__device__ __half w_fc2 [256*1024];

// ============================ helpers ============================
__device__ __forceinline__ uint32_t smem_u32(const void* p) {
    uint32_t a;
    asm("{ .reg .u64 t; cvta.to.shared.u64 t, %1; cvt.u32.u64 %0, t; }" : "=r"(a) : "l"(p));
    return a;
}
__device__ __forceinline__ uint32_t f2h2(float a, float b) {
    __half2 h = __floats2half2_rn(a, b);
    return *reinterpret_cast<uint32_t*>(&h);
}
__device__ __forceinline__ void ldsm4(uint32_t (&r)[4], uint32_t addr) {
    asm volatile("ldmatrix.sync.aligned.m8n8.x4.shared.b16 {%0,%1,%2,%3}, [%4];"
                 : "=r"(r[0]), "=r"(r[1]), "=r"(r[2]), "=r"(r[3]) : "r"(addr));
}
__device__ __forceinline__ void ldsm4t(uint32_t (&r)[4], uint32_t addr) {
    asm volatile("ldmatrix.sync.aligned.m8n8.x4.trans.shared.b16 {%0,%1,%2,%3}, [%4];"
                 : "=r"(r[0]), "=r"(r[1]), "=r"(r[2]), "=r"(r[3]) : "r"(addr));
}
__device__ __forceinline__ void mma16816h(uint32_t* d, const uint32_t* a, uint32_t b0, uint32_t b1) {
    asm volatile("mma.sync.aligned.m16n8k16.row.col.f16.f16.f16.f16 "
                 "{%0,%1},{%2,%3,%4,%5},{%6,%7},{%0,%1};"
                 : "+r"(d[0]), "+r"(d[1])
                 : "r"(a[0]), "r"(a[1]), "r"(a[2]), "r"(a[3]), "r"(b0), "r"(b1));
}
#define CP_A16(dst, src) asm volatile("cp.async.cg.shared.global [%0], [%1], 16;" :: "r"(dst), "l"(src))
#define CP_COMMIT()      asm volatile("cp.async.commit_group;")
#define CP_WAIT(n)       asm volatile("cp.async.wait_group %0;" :: "n"(n))

// ============================ fp16 GEMM, cp.async 3-stage, f16 accumulators ============================
// C[m][n] = sum_k A[m][k]*W[n][k].  BM=BN=128, BK=32, 256 thr (2x4 warps), warp tile 64x32.
#define LDSTR 40
#define SSZ   (128*LDSTR)                 // halves per tensor per stage
#define SMEM_DYN (3*2*SSZ*2)              // 61440 bytes

template <class Epi>
__global__ __launch_bounds__(256, 2) void hgemm(const __half* __restrict__ A,
                                                const __half* __restrict__ W,
                                                int K, Epi epi) {
    extern __shared__ __half sm[];
    int tid = threadIdx.x, lane = tid & 31, wid = tid >> 5;
    int wm = wid >> 2, wn = wid & 3;
    int bm = blockIdx.y << 7, bn = blockIdx.x << 7;
    int NC = K >> 5;
    uint32_t smb = smem_u32(sm);

    auto issue = [&](int st, int ic) {
        int k0 = ic << 5;
        uint32_t sb = smb + st * (2 * SSZ) * 2;
        #pragma unroll
        for (int j = 0; j < 2; j++) {
            int ch = tid + (j << 8);
            int row = ch >> 2, cq = ch & 3;
            uint32_t da = sb + (row * LDSTR + cq * 8) * 2;
            CP_A16(da, A + (size_t)(bm + row) * K + k0 + cq * 8);
            CP_A16(da + SSZ * 2, W + (size_t)(bn + row) * K + k0 + cq * 8);
        }
        CP_COMMIT();
    };

    issue(0, 0); issue(1, 1);
    uint32_t acch[4][4][2] = {};
    for (int ic = 0; ic < NC; ic++) {
        if (ic + 1 < NC) CP_WAIT(1); else CP_WAIT(0);
        __syncthreads();
        if (ic + 2 < NC) issue((ic + 2) % 3, ic + 2);
        uint32_t baseA = smb + (ic % 3) * (2 * SSZ) * 2;
        uint32_t baseB = baseA + SSZ * 2;
        #pragma unroll
        for (int ks = 0; ks < 2; ks++) {
            uint32_t af[4][4], bf[2][4];
            #pragma unroll
            for (int mt = 0; mt < 4; mt++)
                ldsm4(af[mt], baseA + (((wm*64 + mt*16 + (lane & 15)) * LDSTR + ks*16 + (lane >> 4)*8) << 1));
            #pragma unroll
            for (int bt = 0; bt < 2; bt++)
                ldsm4(bf[bt], baseB + (((wn*32 + bt*16 + (lane & 15)) * LDSTR + ks*16 + (lane >> 4)*8) << 1));
            #pragma unroll
            for (int mt = 0; mt < 4; mt++)
                #pragma unroll
                for (int nt = 0; nt < 4; nt++)
                    mma16816h(acch[mt][nt], af[mt], bf[nt>>1][nt&1], bf[nt>>1][(nt&1)+2]);
        }
    }
    int g = lane >> 2, tg = lane & 3;

    if constexpr (Epi::STAGED) {
        // FC2: val = acc + bias + xf2, then NCHW-coalesced write via smem stage (2 half-tiles)
        float* stg = (float*)sm;
        int b = bm >> 12, hw0 = bm & 4095;
        for (int p = 0; p < 2; p++) {
            __syncthreads();
            if (wm == p) {
                #pragma unroll
                for (int mt = 0; mt < 4; mt++) {
                    int lr = mt * 16 + g;
                    size_t gr0 = (size_t)(bm + p * 64 + lr) * CH;
                    size_t gr1 = gr0 + 8 * CH;
                    #pragma unroll
                    for (int nt = 0; nt < 4; nt++) {
                        int c = wn * 32 + nt * 8 + tg * 2;
                        __half2 h0 = *(__half2*)&acch[mt][nt][0];
                        __half2 h1 = *(__half2*)&acch[mt][nt][1];
                        float2 x0 = *(const float2*)&g_xf2[gr0 + bn + c];
                        float2 x1 = *(const float2*)&g_xf2[gr1 + bn + c];
                        stg[lr * 132 + c]           = __low2float(h0)  + epi.bias[bn + c]     + x0.x;
                        stg[lr * 132 + c + 1]       = __high2float(h0) + epi.bias[bn + c + 1] + x0.y;
                        stg[(lr + 8) * 132 + c]     = __low2float(h1)  + epi.bias[bn + c]     + x1.x;
                        stg[(lr + 8) * 132 + c + 1] = __high2float(h1) + epi.bias[bn + c + 1] + x1.y;
                    }
                }
            }
            __syncthreads();
            #pragma unroll 1
            for (int i = 0; i < 32; i++) {
                int idx = tid + (i << 8);
                int row = idx & 63, c = idx >> 6;
                epi.out[((size_t)(b * CH + bn + c) << 12) + hw0 + p * 64 + row] = stg[row * 132 + c];
            }
        }
    } else {
        #pragma unroll
        for (int mt = 0; mt < 4; mt++) {
            int M0 = bm + wm * 64 + mt * 16;
            #pragma unroll
            for (int nt = 0; nt < 4; nt++) {
                int N0 = bn + wn * 32 + nt * 8 + tg * 2;
                __half2 h0 = *(__half2*)&acch[mt][nt][0];
                __half2 h1 = *(__half2*)&acch[mt][nt][1];
                epi.pair(M0 + g,     N0, __low2float(h0), __high2float(h0));
                epi.pair(M0 + g + 8, N0, __low2float(h1), __high2float(h1));
            }
        }
    }
}

// ============================ epilogues (pair interface: c even) ============================
struct EpiQKV {
    const float* bias;
    static constexpr bool STAGED = false;
    __device__ void pair(int r, int c, float a0, float a1) const {
        float va = a0 + bias[c], vb = a1 + bias[c + 1];
        int part = c >> 8, head = (c >> 5) & 7, d = c & 31;
        int win = r >> 6, pos = r & 63;
        size_t o = (size_t)(win * NHEAD + head) * 2048 + pos * 32 + d;
        if (part == 0)      *(uint32_t*)&g_q[o] = f2h2(va * 4.0f, vb * 4.0f);
        else if (part == 1) *(uint32_t*)&g_k[o] = f2h2(va, vb);
        else {
            uint32_t hv = f2h2(va, vb);
            *(uint32_t*)&g_v[o] = hv;
            int b = win >> 6, wh = (win >> 3) & 7, ww = win & 7;
            int ii = pos >> 3, jj = pos & 7;
            int R = ii * 8 + wh, Cc = jj * 8 + ww;
            *(uint32_t*)&g_img_h[(((size_t)((b << 6) + R) << 6) + Cc) * CH + (c - 512)] = hv;
        }
    }
};
struct EpiProj {
    const float* bias;
    static constexpr bool STAGED = false;
    __device__ void pair(int r, int c, float a0, float a1) const {
        int win = r >> 6, pos = r & 63;
        int b = win >> 6, wh = (win >> 3) & 7, ww = win & 7;
        int ii = pos >> 3, jj = pos & 7;
        int t = (b << 12) + ((wh * 8 + ii) << 6) + ww * 8 + jj;
        size_t o = (size_t)t * CH + c;
        float2 xf = *(const float2*)&g_xf[o];
        float2 res = make_float2(xf.x + a0 + bias[c], xf.y + a1 + bias[c + 1]);
        *(float2*)&g_xf2[o] = res;
    }
};
struct EpiFC1 {
    const float* bias;
    static constexpr bool STAGED = false;
    __device__ void pair(int r, int c, float a0, float a1) const {
        float x0 = a0 + bias[c], x1 = a1 + bias[c + 1];
        float g0 = 0.5f * x0 * (1.0f + erff(x0 * 0.70710678118654752f));
        float g1 = 0.5f * x1 * (1.0f + erff(x1 * 0.70710678118654752f));
        *(uint32_t*)&g_h1_h[(size_t)r * HID + c] = f2h2(g0, g1);
    }
};
struct EpiFC2 {
    const float* bias;
    float* out;
    static constexpr bool STAGED = true;
    __device__ void pair(int, int, float, float) const {}
};

// ---------------- all weights fp32 -> fp16, one vectorized launch ----------------
__global__ __launch_bounds__(256) void cvt_all(const float* __restrict__ qkv,
                                               const float* __restrict__ proj,
                                               const float* __restrict__ fc1,
                                               const float* __restrict__ fc2) {
    int i4 = blockIdx.x * 256 + threadIdx.x;    // 196608 float4 units
    int i = i4 * 4;
    const float* s;
    __half* d;
    if (i < 196608)      { s = qkv  + i;          d = w_qkv  + i; }
    else if (i < 262144) { s = proj + (i-196608); d = w_proj + (i-196608); }
    else if (i < 524288) { s = fc1  + (i-262144); d = w_fc1  + (i-262144); }
    else                 { s = fc2  + (i-524288); d = w_fc2  + (i-524288); }
    float4 v = *(const float4*)s;
    uint2 h;
    h.x = f2h2(v.x, v.y);
    h.y = f2h2(v.z, v.w);
    *(uint2*)d = h;
}

// ---------------- relative position bias prep ----------------
__global__ void bias_kernel(const float* __restrict__ rpb) {
    int idx = blockIdx.x * 256 + threadIdx.x;
    int h_ = idx >> 12, n = (idx >> 6) & 63, m = idx & 63;
    int di = (n >> 3) - (m >> 3) + 7;
    int dj = (n & 7) - (m & 7) + 7;
    g_bias[idx] = rpb[(di * 15 + dj) * NHEAD + h_];
}

// ---------------- LayerNorm 1 ----------------
__global__ __launch_bounds__(256) void ln1_kernel(const float* __restrict__ x,
                                                  const float* __restrict__ gw,
                                                  const float* __restrict__ gb) {
    __shared__ float tx[256][33];
    int t0 = blockIdx.x * 32;
    int b = t0 >> 12, hw0 = t0 & 4095;
    int tid = threadIdx.x;
    #pragma unroll
    for (int j = 0; j < 32; j++) {
        int idx = j * 256 + tid;
        int c = idx >> 5, i = idx & 31;
        tx[c][i] = x[((size_t)(b * CH + c) << 12) + hw0 + i];
    }
    __syncthreads();
    int lane = tid & 31, w = tid >> 5;
    #pragma unroll
    for (int q = 0; q < 4; q++) {
        int i = w * 4 + q;
        float s = 0.f, s2 = 0.f;
        #pragma unroll
        for (int k = 0; k < 8; k++) { float v = tx[lane + 32 * k][i]; s += v; s2 += v * v; }
        #pragma unroll
        for (int o = 16; o; o >>= 1) { s += __shfl_xor_sync(~0u, s, o); s2 += __shfl_xor_sync(~0u, s2, o); }
        float mean = s * (1.f / CH);
        float inv = rsqrtf(s2 * (1.f / CH) - mean * mean + 1e-5f);
        int t = t0 + i;
        int hw = hw0 + i, hh = hw >> 6, wc = hw & 63;
        int wh = hh >> 3, ii = hh & 7, ww = wc >> 3, jj = wc & 7;
        int r = ((b * 64 + wh * 8 + ww) << 6) + (ii << 3) + jj;
        #pragma unroll
        for (int k = 0; k < 8; k++) {
            int c = lane + 32 * k;
            float v = tx[c][i];
            g_xf[(size_t)t * CH + c] = v;
            g_xnw_h[(size_t)r * CH + c] = __float2half((v - mean) * inv * gw[c] + gb[c]);
        }
    }
}

// ---------------- LayerNorm 2: one warp per token, no block sync ----------------
__global__ __launch_bounds__(256) void ln2_kernel(const float* __restrict__ gw,
                                                  const float* __restrict__ gb) {
    int lane = threadIdx.x & 31, w = threadIdx.x >> 5;
    int t = blockIdx.x * 8 + w;
    const float* src = g_xf2 + (size_t)t * CH + lane * 8;
    float4 v0 = *(const float4*)src;
    float4 v1 = *(const float4*)(src + 4);
    float s  = v0.x + v0.y + v0.z + v0.w + v1.x + v1.y + v1.z + v1.w;
    float s2 = v0.x*v0.x + v0.y*v0.y + v0.z*v0.z + v0.w*v0.w
             + v1.x*v1.x + v1.y*v1.y + v1.z*v1.z + v1.w*v1.w;
    #pragma unroll
    for (int o = 16; o; o >>= 1) { s += __shfl_xor_sync(~0u, s, o); s2 += __shfl_xor_sync(~0u, s2, o); }
    float mean = s * (1.f / CH);
    float inv = rsqrtf(s2 * (1.f / CH) - mean * mean + 1e-5f);
    int c0 = lane * 8;
    float4 gwv0 = *(const float4*)(gw + c0), gwv1 = *(const float4*)(gw + c0 + 4);
    float4 gbv0 = *(const float4*)(gb + c0), gbv1 = *(const float4*)(gb + c0 + 4);
    uint4 outv;
    outv.x = f2h2((v0.x - mean) * inv * gwv0.x + gbv0.x, (v0.y - mean) * inv * gwv0.y + gbv0.y);
    outv.y = f2h2((v0.z - mean) * inv * gwv0.z + gbv0.z, (v0.w - mean) * inv * gwv0.w + gbv0.w);
    outv.z = f2h2((v1.x - mean) * inv * gwv1.x + gbv1.x, (v1.y - mean) * inv * gwv1.y + gbv1.y);
    outv.w = f2h2((v1.z - mean) * inv * gwv1.z + gbv1.z, (v1.w - mean) * inv * gwv1.w + gbv1.w);
    *(uint4*)(g_ln2_h + (size_t)t * CH + c0) = outv;
}

// ---------------- tensor-core attention: one block per (win, head), 4 warps, f16 acc ----------------
__global__ __launch_bounds__(128) void attn_mma() {
    int win = blockIdx.x >> 3, head = blockIdx.x & 7;
    __shared__ __half sq[64 * 40], sk[64 * 40], sv[64 * 40];
    __shared__ float sb[64 * 64];
    int tid = threadIdx.x, lane = tid & 31, w = tid >> 5;

    const __half* qb = g_q + (size_t)(win * NHEAD + head) * 2048;
    const __half* kb = g_k + (size_t)(win * NHEAD + head) * 2048;
    const __half* vb = g_v + (size_t)(win * NHEAD + head) * 2048;
    #pragma unroll
    for (int j = 0; j < 2; j++) {
        int ch = tid + (j << 7);
        int row = ch >> 2, cq = ch & 3;
        *(uint4*)&sq[row * 40 + cq * 8] = *(const uint4*)(qb + row * 32 + cq * 8);
        *(uint4*)&sk[row * 40 + cq * 8] = *(const uint4*)(kb + row * 32 + cq * 8);
        *(uint4*)&sv[row * 40 + cq * 8] = *(const uint4*)(vb + row * 32 + cq * 8);
    }
    const float4* bb = (const float4*)(g_bias + head * 4096);
    #pragma unroll
    for (int j = 0; j < 8; j++)
        ((float4*)sb)[tid + (j << 7)] = bb[tid + (j << 7)];
    __syncthreads();

    uint32_t bq = smem_u32(sq), bk = smem_u32(sk), bv = smem_u32(sv);
    int g = lane >> 2, tg = lane & 3;

    uint32_t aq[2][4];
    #pragma unroll
    for (int t = 0; t < 2; t++)
        ldsm4(aq[t], bq + (((16 * w + (lane & 15)) * 40 + t * 16 + (lane >> 4) * 8) << 1));

    uint32_t acch[8][2] = {};
    #pragma unroll
    for (int t = 0; t < 2; t++)
        #pragma unroll
        for (int u = 0; u < 4; u++) {
            uint32_t bf[4];
            ldsm4(bf, bk + (((16 * u + (lane & 15)) * 40 + t * 16 + (lane >> 4) * 8) << 1));
            mma16816h(acch[2 * u],     aq[t], bf[0], bf[2]);
            mma16816h(acch[2 * u + 1], aq[t], bf[1], bf[3]);
        }

    // unpack to f32, + bias, softmax
    float acc[8][4];
    int r0 = 16 * w + g, r1 = r0 + 8;
    float mx0 = -1e30f, mx1 = -1e30f;
    #pragma unroll
    for (int s = 0; s < 8; s++) {
        __half2 h0 = *(__half2*)&acch[s][0];
        __half2 h1 = *(__half2*)&acch[s][1];
        acc[s][0] = __low2float(h0)  + sb[r0 * 64 + 8 * s + tg * 2];
        acc[s][1] = __high2float(h0) + sb[r0 * 64 + 8 * s + tg * 2 + 1];
        acc[s][2] = __low2float(h1)  + sb[r1 * 64 + 8 * s + tg * 2];
        acc[s][3] = __high2float(h1) + sb[r1 * 64 + 8 * s + tg * 2 + 1];
        mx0 = fmaxf(mx0, fmaxf(acc[s][0], acc[s][1]));
        mx1 = fmaxf(mx1, fmaxf(acc[s][2], acc[s][3]));
    }
    mx0 = fmaxf(mx0, __shfl_xor_sync(~0u, mx0, 1)); mx0 = fmaxf(mx0, __shfl_xor_sync(~0u, mx0, 2));
    mx1 = fmaxf(mx1, __shfl_xor_sync(~0u, mx1, 1)); mx1 = fmaxf(mx1, __shfl_xor_sync(~0u, mx1, 2));
    float sm0 = 0.f, sm1 = 0.f;
    #pragma unroll
    for (int s = 0; s < 8; s++) {
        acc[s][0] = __expf(acc[s][0] - mx0); acc[s][1] = __expf(acc[s][1] - mx0);
        acc[s][2] = __expf(acc[s][2] - mx1); acc[s][3] = __expf(acc[s][3] - mx1);
        sm0 += acc[s][0] + acc[s][1];
        sm1 += acc[s][2] + acc[s][3];
    }
    sm0 += __shfl_xor_sync(~0u, sm0, 1); sm0 += __shfl_xor_sync(~0u, sm0, 2);
    sm1 += __shfl_xor_sync(~0u, sm1, 1); sm1 += __shfl_xor_sync(~0u, sm1, 2);
    float iv0 = 1.f / sm0, iv1 = 1.f / sm1;
    uint32_t ap[4][4];
    #pragma unroll
    for (int t = 0; t < 4; t++) {
        ap[t][0] = f2h2(acc[2*t][0]*iv0,   acc[2*t][1]*iv0);
        ap[t][1] = f2h2(acc[2*t][2]*iv1,   acc[2*t][3]*iv1);
        ap[t][2] = f2h2(acc[2*t+1][0]*iv0, acc[2*t+1][1]*iv0);
        ap[t][3] = f2h2(acc[2*t+1][2]*iv1, acc[2*t+1][3]*iv1);
    }

    uint32_t oacch[4][2] = {};
    #pragma unroll
    for (int t = 0; t < 4; t++)
        #pragma unroll
        for (int np = 0; np < 2; np++) {
            uint32_t bf[4];
            ldsm4t(bf, bv + (((16 * t + (lane & 15)) * 40 + np * 16 + (lane >> 4) * 8) << 1));
            mma16816h(oacch[2 * np],     ap[t], bf[0], bf[1]);
            mma16816h(oacch[2 * np + 1], ap[t], bf[2], bf[3]);
        }

    __half* ob = g_att_h + ((size_t)win * 64) * 256 + head * 32;
    #pragma unroll
    for (int n = 0; n < 4; n++) {
        *(uint32_t*)&ob[(size_t)r0 * 256 + 8 * n + tg * 2] = oacch[n][0];
        *(uint32_t*)&ob[(size_t)r1 * 256 + 8 * n + tg * 2] = oacch[n][1];
    }
}

// ---------------- depthwise 9x9 conv + unfold, half2 datapath; accumulates into g_att_h ----------------
__global__ __launch_bounds__(256) void gaze_conv_kernel(const float* __restrict__ gw,
                                                        const float* __restrict__ gb) {
    int bidx = blockIdx.x;                 // 16*64*8
    int cc = bidx & 7;
    int tile = (bidx >> 3) & 63;
    int b = bidx >> 9;
    int tr = (tile >> 3) << 3;
    int tc = (tile & 7) << 3;
    int ch0 = cc << 5;

    __shared__ __half2 sin_h[16][16][16];  // [py][px][ch2] = 16 KB
    __shared__ __half2 swt_h[81][16];      // 5.2 KB
    int tid = threadIdx.x;

    for (int i = tid; i < 81 * 16; i += 256) {
        int tap = i >> 4, c2 = i & 15;
        swt_h[tap][c2] = __floats2half2_rn(gw[tap * CH + ch0 + 2 * c2],
                                           gw[tap * CH + ch0 + 2 * c2 + 1]);
    }
    for (int i = tid; i < 16 * 16 * 16; i += 256) {
        int c2 = i & 15, px = (i >> 4) & 15, py = i >> 8;
        int R = tr - 4 + py, Cc = tc - 4 + px;
        __half2 v = __floats2half2_rn(0.f, 0.f);
        if (R >= 0 && R < 64 && Cc >= 0 && Cc < 64)
            v = *(const __half2*)&g_img_h[(((size_t)((b << 6) + R) << 6) + Cc) * CH + ch0 + 2 * c2];
        sin_h[py][px][c2] = v;
    }
    __syncthreads();

    int c2 = tid & 15, px = (tid >> 4) & 7, pyh = tid >> 7;   // pyh in {0,1}
    __half2 acc[4];
    #pragma unroll
    for (int i = 0; i < 4; i++) acc[i] = __floats2half2_rn(0.f, 0.f);
    #pragma unroll
    for (int dx = 0; dx < 9; dx++) {
        __half2 col[12];
        #pragma unroll
        for (int ry = 0; ry < 12; ry++) col[ry] = sin_h[pyh * 4 + ry][px + dx][c2];
        #pragma unroll
        for (int dy = 0; dy < 9; dy++) {
            __half2 wv = swt_h[dy * 9 + dx][c2];
            #pragma unroll
            for (int py = 0; py < 4; py++) acc[py] = __hfma2(col[py + dy], wv, acc[py]);
        }
    }
    __half2 bias2 = __floats2half2_rn(gb[ch0 + 2 * c2], gb[ch0 + 2 * c2 + 1]);
    #pragma unroll
    for (int py = 0; py < 4; py++) {
        int R = tr + pyh * 4 + py, Cc = tc + px;
        int wh = R & 7, ii = R >> 3, ww = Cc & 7, jj = Cc >> 3;
        int r = ((b * 64 + wh * 8 + ww) << 6) + (ii << 3) + jj;
        size_t o = (size_t)r * CH + ch0 + 2 * c2;
        __half2 old = *(__half2*)&g_att_h[o];
        *(__half2*)&g_att_h[o] = __hadd2(old, __hadd2(acc[py], bias2));
    }
}

// ---------------- host launch ----------------
extern "C" void kernel_launch(void* const* d_in, const int* in_sizes, int n_in,
                              void* d_out, int out_size) {
    int off = (n_in >= 18) ? 2 : 0;
    const float* x       = (const float*)d_in[off + 0];
    const float* norm1_g = (const float*)d_in[off + 1];
    const float* norm1_b = (const float*)d_in[off + 2];
    const float* qkv_w   = (const float*)d_in[off + 3];
    const float* qkv_b   = (const float*)d_in[off + 4];
    const float* rpb     = (const float*)d_in[off + 5];
    const float* proj_w  = (const float*)d_in[off + 6];
    const float* proj_b  = (const float*)d_in[off + 7];
    const float* gaze_w  = (const float*)d_in[off + 8];
    const float* gaze_b  = (const float*)d_in[off + 9];
    const float* norm2_g = (const float*)d_in[off + 10];
    const float* norm2_b = (const float*)d_in[off + 11];
    const float* fc1_w   = (const float*)d_in[off + 12];
    const float* fc1_b   = (const float*)d_in[off + 13];
    const float* fc2_w   = (const float*)d_in[off + 14];
    const float* fc2_b   = (const float*)d_in[off + 15];

    __half *pw_qkv, *pw_proj, *pw_fc1, *pw_fc2;
    __half *p_xnw, *p_atth, *p_ln2, *p_h1;
    cudaGetSymbolAddress((void**)&pw_qkv, w_qkv);
    cudaGetSymbolAddress((void**)&pw_proj, w_proj);
    cudaGetSymbolAddress((void**)&pw_fc1, w_fc1);
    cudaGetSymbolAddress((void**)&pw_fc2, w_fc2);
    cudaGetSymbolAddress((void**)&p_xnw, g_xnw_h);
    cudaGetSymbolAddress((void**)&p_atth, g_att_h);
    cudaGetSymbolAddress((void**)&p_ln2, g_ln2_h);
    cudaGetSymbolAddress((void**)&p_h1,  g_h1_h);

    cudaFuncSetAttribute((const void*)hgemm<EpiQKV>,  cudaFuncAttributeMaxDynamicSharedMemorySize, SMEM_DYN);
    cudaFuncSetAttribute((const void*)hgemm<EpiProj>, cudaFuncAttributeMaxDynamicSharedMemorySize, SMEM_DYN);
    cudaFuncSetAttribute((const void*)hgemm<EpiFC1>,  cudaFuncAttributeMaxDynamicSharedMemorySize, SMEM_DYN);
    cudaFuncSetAttribute((const void*)hgemm<EpiFC2>,  cudaFuncAttributeMaxDynamicSharedMemorySize, SMEM_DYN);

    cvt_all<<<768, 256>>>(qkv_w, proj_w, fc1_w, fc2_w);
    bias_kernel<<<128, 256>>>(rpb);
    ln1_kernel<<<2048, 256>>>(x, norm1_g, norm1_b);
    hgemm<EpiQKV><<<dim3(6, 512), 256, SMEM_DYN>>>(p_xnw, pw_qkv, 256, EpiQKV{qkv_b});
    attn_mma<<<8192, 128>>>();
    gaze_conv_kernel<<<8192, 256>>>(gaze_w, gaze_b);
    hgemm<EpiProj><<<dim3(2, 512), 256, SMEM_DYN>>>(p_atth, pw_proj, 256, EpiProj{proj_b});
    ln2_kernel<<<8192, 256>>>(norm2_g, norm2_b);
    hgemm<EpiFC1><<<dim3(8, 512), 256, SMEM_DYN>>>(p_ln2, pw_fc1, 256, EpiFC1{fc1_b});
    hgemm<EpiFC2><<<dim3(2, 512), 256, SMEM_DYN>>>(p_h1, pw_fc2, 1024, EpiFC2{fc2_b, (float*)d_out});
}

// round 15
// speedup vs baseline: 1.2630x; 1.0262x over previous
#include <cuda_runtime.h>
#include <cuda_fp16.h>
#include <math.h>
#include <stdint.h>

#define BATCH   16
#define CH      256
#define TOKENS  (BATCH*64*64)      // 65536
#define HID     1024
#define NHEAD   8
#define NTOK    64

// ---------------- scratch (device globals; allocation-free) ----------------
__device__ float  g_xf2 [TOKENS*CH];   // after proj residual, token-major (fp32)
__device__ float  g_bias[NHEAD*NTOK*NTOK];

__device__ __half g_xf_h [TOKENS*CH];  // shortcut, token-major (fp16)
__device__ __half g_xnw_h[TOKENS*CH];  // LN1 out, windowed
__device__ __half g_q   [TOKENS*CH];   // [win][head][pos][hd], pre-scaled
__device__ __half g_k   [TOKENS*CH];
__device__ __half g_v   [TOKENS*CH];
__device__ __half g_img_h[TOKENS*CH];  // folded image NHWC
__device__ __half g_att_h[TOKENS*CH];  // attn out; gaze accumulates in-place
__device__ __half g_ln2_h[TOKENS*CH];
__device__ __half g_h1_h [TOKENS*HID];

__device__ __half w_qkv [768*256];
__device__ __half w_proj[256*256];
__device__ __half w_fc1 [1024*256];
__device__ __half w_fc2 [256*1024];

// ============================ helpers ============================
__device__ __forceinline__ uint32_t smem_u32(const void* p) {
    uint32_t a;
    asm("{ .reg .u64 t; cvta.to.shared.u64 t, %1; cvt.u32.u64 %0, t; }" : "=r"(a) : "l"(p));
    return a;
}
__device__ __forceinline__ uint32_t f2h2(float a, float b) {
    __half2 h = __floats2half2_rn(a, b);
    return *reinterpret_cast<uint32_t*>(&h);
}
__device__ __forceinline__ void ldsm4(uint32_t (&r)[4], uint32_t addr) {
    asm volatile("ldmatrix.sync.aligned.m8n8.x4.shared.b16 {%0,%1,%2,%3}, [%4];"
                 : "=r"(r[0]), "=r"(r[1]), "=r"(r[2]), "=r"(r[3]) : "r"(addr));
}
__device__ __forceinline__ void ldsm4t(uint32_t (&r)[4], uint32_t addr) {
    asm volatile("ldmatrix.sync.aligned.m8n8.x4.trans.shared.b16 {%0,%1,%2,%3}, [%4];"
                 : "=r"(r[0]), "=r"(r[1]), "=r"(r[2]), "=r"(r[3]) : "r"(addr));
}
__device__ __forceinline__ void mma16816h(uint32_t* d, const uint32_t* a, uint32_t b0, uint32_t b1) {
    asm volatile("mma.sync.aligned.m16n8k16.row.col.f16.f16.f16.f16 "
                 "{%0,%1},{%2,%3,%4,%5},{%6,%7},{%0,%1};"
                 : "+r"(d[0]), "+r"(d[1])
                 : "r"(a[0]), "r"(a[1]), "r"(a[2]), "r"(a[3]), "r"(b0), "r"(b1));
}
#define CP_A16(dst, src) asm volatile("cp.async.cg.shared.global [%0], [%1], 16;" :: "r"(dst), "l"(src))
#define CP_COMMIT()      asm volatile("cp.async.commit_group;")
#define CP_WAIT(n)       asm volatile("cp.async.wait_group %0;" :: "n"(n))

// ============================ fp16 GEMM, cp.async 3-stage, f16 accumulators ============================
// C[m][n] = sum_k A[m][k]*W[n][k].  BM=BN=128, BK=32, 256 thr (2x4 warps), warp tile 64x32.
#define LDSTR 40
#define SSZ   (128*LDSTR)                 // halves per tensor per stage
#define SMEM_DYN (3*2*SSZ*2)              // 61440 bytes

template <class Epi>
__global__ __launch_bounds__(256, 2) void hgemm(const __half* __restrict__ A,
                                                const __half* __restrict__ W,
                                                int K, Epi epi) {
    extern __shared__ __half sm[];
    int tid = threadIdx.x, lane = tid & 31, wid = tid >> 5;
    int wm = wid >> 2, wn = wid & 3;
    int bm = blockIdx.y << 7, bn = blockIdx.x << 7;
    int NC = K >> 5;
    uint32_t smb = smem_u32(sm);

    auto issue = [&](int st, int ic) {
        int k0 = ic << 5;
        uint32_t sb = smb + st * (2 * SSZ) * 2;
        #pragma unroll
        for (int j = 0; j < 2; j++) {
            int ch = tid + (j << 8);
            int row = ch >> 2, cq = ch & 3;
            uint32_t da = sb + (row * LDSTR + cq * 8) * 2;
            CP_A16(da, A + (size_t)(bm + row) * K + k0 + cq * 8);
            CP_A16(da + SSZ * 2, W + (size_t)(bn + row) * K + k0 + cq * 8);
        }
        CP_COMMIT();
    };

    issue(0, 0); issue(1, 1);
    uint32_t acch[4][4][2] = {};
    for (int ic = 0; ic < NC; ic++) {
        if (ic + 1 < NC) CP_WAIT(1); else CP_WAIT(0);
        __syncthreads();
        if (ic + 2 < NC) issue((ic + 2) % 3, ic + 2);
        uint32_t baseA = smb + (ic % 3) * (2 * SSZ) * 2;
        uint32_t baseB = baseA + SSZ * 2;
        #pragma unroll
        for (int ks = 0; ks < 2; ks++) {
            uint32_t af[4][4], bf[2][4];
            #pragma unroll
            for (int mt = 0; mt < 4; mt++)
                ldsm4(af[mt], baseA + (((wm*64 + mt*16 + (lane & 15)) * LDSTR + ks*16 + (lane >> 4)*8) << 1));
            #pragma unroll
            for (int bt = 0; bt < 2; bt++)
                ldsm4(bf[bt], baseB + (((wn*32 + bt*16 + (lane & 15)) * LDSTR + ks*16 + (lane >> 4)*8) << 1));
            #pragma unroll
            for (int mt = 0; mt < 4; mt++)
                #pragma unroll
                for (int nt = 0; nt < 4; nt++)
                    mma16816h(acch[mt][nt], af[mt], bf[nt>>1][nt&1], bf[nt>>1][(nt&1)+2]);
        }
    }
    int g = lane >> 2, tg = lane & 3;

    if constexpr (Epi::STAGED) {
        // FC2: val = acc + bias + xf2, then NCHW-coalesced write via smem stage (2 half-tiles)
        float* stg = (float*)sm;
        int b = bm >> 12, hw0 = bm & 4095;
        for (int p = 0; p < 2; p++) {
            __syncthreads();
            if (wm == p) {
                #pragma unroll
                for (int mt = 0; mt < 4; mt++) {
                    int lr = mt * 16 + g;
                    size_t gr0 = (size_t)(bm + p * 64 + lr) * CH;
                    size_t gr1 = gr0 + 8 * CH;
                    #pragma unroll
                    for (int nt = 0; nt < 4; nt++) {
                        int c = wn * 32 + nt * 8 + tg * 2;
                        __half2 h0 = *(__half2*)&acch[mt][nt][0];
                        __half2 h1 = *(__half2*)&acch[mt][nt][1];
                        float2 x0 = *(const float2*)&g_xf2[gr0 + bn + c];
                        float2 x1 = *(const float2*)&g_xf2[gr1 + bn + c];
                        stg[lr * 132 + c]           = __low2float(h0)  + epi.bias[bn + c]     + x0.x;
                        stg[lr * 132 + c + 1]       = __high2float(h0) + epi.bias[bn + c + 1] + x0.y;
                        stg[(lr + 8) * 132 + c]     = __low2float(h1)  + epi.bias[bn + c]     + x1.x;
                        stg[(lr + 8) * 132 + c + 1] = __high2float(h1) + epi.bias[bn + c + 1] + x1.y;
                    }
                }
            }
            __syncthreads();
            #pragma unroll 1
            for (int i = 0; i < 32; i++) {
                int idx = tid + (i << 8);
                int row = idx & 63, c = idx >> 6;
                epi.out[((size_t)(b * CH + bn + c) << 12) + hw0 + p * 64 + row] = stg[row * 132 + c];
            }
        }
    } else {
        #pragma unroll
        for (int mt = 0; mt < 4; mt++) {
            int M0 = bm + wm * 64 + mt * 16;
            #pragma unroll
            for (int nt = 0; nt < 4; nt++) {
                int N0 = bn + wn * 32 + nt * 8 + tg * 2;
                __half2 h0 = *(__half2*)&acch[mt][nt][0];
                __half2 h1 = *(__half2*)&acch[mt][nt][1];
                epi.pair(M0 + g,     N0, __low2float(h0), __high2float(h0));
                epi.pair(M0 + g + 8, N0, __low2float(h1), __high2float(h1));
            }
        }
    }
}

// ============================ epilogues (pair interface: c even) ============================
struct EpiQKV {
    const float* bias;
    static constexpr bool STAGED = false;
    __device__ void pair(int r, int c, float a0, float a1) const {
        float va = a0 + bias[c], vb = a1 + bias[c + 1];
        int part = c >> 8, head = (c >> 5) & 7, d = c & 31;
        int win = r >> 6, pos = r & 63;
        size_t o = (size_t)(win * NHEAD + head) * 2048 + pos * 32 + d;
        if (part == 0)      *(uint32_t*)&g_q[o] = f2h2(va * 4.0f, vb * 4.0f);
        else if (part == 1) *(uint32_t*)&g_k[o] = f2h2(va, vb);
        else {
            uint32_t hv = f2h2(va, vb);
            *(uint32_t*)&g_v[o] = hv;
            int b = win >> 6, wh = (win >> 3) & 7, ww = win & 7;
            int ii = pos >> 3, jj = pos & 7;
            int R = ii * 8 + wh, Cc = jj * 8 + ww;
            *(uint32_t*)&g_img_h[(((size_t)((b << 6) + R) << 6) + Cc) * CH + (c - 512)] = hv;
        }
    }
};
struct EpiProj {
    const float* bias;
    static constexpr bool STAGED = false;
    __device__ void pair(int r, int c, float a0, float a1) const {
        int win = r >> 6, pos = r & 63;
        int b = win >> 6, wh = (win >> 3) & 7, ww = win & 7;
        int ii = pos >> 3, jj = pos & 7;
        int t = (b << 12) + ((wh * 8 + ii) << 6) + ww * 8 + jj;
        size_t o = (size_t)t * CH + c;
        __half2 xf = *(const __half2*)&g_xf_h[o];
        float2 res = make_float2(__low2float(xf) + a0 + bias[c],
                                 __high2float(xf) + a1 + bias[c + 1]);
        *(float2*)&g_xf2[o] = res;
    }
};
struct EpiFC1 {
    const float* bias;
    static constexpr bool STAGED = false;
    __device__ void pair(int r, int c, float a0, float a1) const {
        float x0 = a0 + bias[c], x1 = a1 + bias[c + 1];
        float g0 = 0.5f * x0 * (1.0f + erff(x0 * 0.70710678118654752f));
        float g1 = 0.5f * x1 * (1.0f + erff(x1 * 0.70710678118654752f));
        *(uint32_t*)&g_h1_h[(size_t)r * HID + c] = f2h2(g0, g1);
    }
};
struct EpiFC2 {
    const float* bias;
    float* out;
    static constexpr bool STAGED = true;
    __device__ void pair(int, int, float, float) const {}
};

// ---------------- all weights fp32 -> fp16, one vectorized launch ----------------
__global__ __launch_bounds__(256) void cvt_all(const float* __restrict__ qkv,
                                               const float* __restrict__ proj,
                                               const float* __restrict__ fc1,
                                               const float* __restrict__ fc2) {
    int i4 = blockIdx.x * 256 + threadIdx.x;    // 196608 float4 units
    int i = i4 * 4;
    const float* s;
    __half* d;
    if (i < 196608)      { s = qkv  + i;          d = w_qkv  + i; }
    else if (i < 262144) { s = proj + (i-196608); d = w_proj + (i-196608); }
    else if (i < 524288) { s = fc1  + (i-262144); d = w_fc1  + (i-262144); }
    else                 { s = fc2  + (i-524288); d = w_fc2  + (i-524288); }
    float4 v = *(const float4*)s;
    uint2 h;
    h.x = f2h2(v.x, v.y);
    h.y = f2h2(v.z, v.w);
    *(uint2*)d = h;
}

// ---------------- relative position bias prep ----------------
__global__ void bias_kernel(const float* __restrict__ rpb) {
    int idx = blockIdx.x * 256 + threadIdx.x;
    int h_ = idx >> 12, n = (idx >> 6) & 63, m = idx & 63;
    int di = (n >> 3) - (m >> 3) + 7;
    int dj = (n & 7) - (m & 7) + 7;
    g_bias[idx] = rpb[(di * 15 + dj) * NHEAD + h_];
}

// ---------------- LayerNorm 1 ----------------
__global__ __launch_bounds__(256) void ln1_kernel(const float* __restrict__ x,
                                                  const float* __restrict__ gw,
                                                  const float* __restrict__ gb) {
    __shared__ float tx[256][33];
    int t0 = blockIdx.x * 32;
    int b = t0 >> 12, hw0 = t0 & 4095;
    int tid = threadIdx.x;
    #pragma unroll
    for (int j = 0; j < 32; j++) {
        int idx = j * 256 + tid;
        int c = idx >> 5, i = idx & 31;
        tx[c][i] = x[((size_t)(b * CH + c) << 12) + hw0 + i];
    }
    __syncthreads();
    int lane = tid & 31, w = tid >> 5;
    #pragma unroll
    for (int q = 0; q < 4; q++) {
        int i = w * 4 + q;
        float s = 0.f, s2 = 0.f;
        #pragma unroll
        for (int k = 0; k < 8; k++) { float v = tx[lane + 32 * k][i]; s += v; s2 += v * v; }
        #pragma unroll
        for (int o = 16; o; o >>= 1) { s += __shfl_xor_sync(~0u, s, o); s2 += __shfl_xor_sync(~0u, s2, o); }
        float mean = s * (1.f / CH);
        float inv = rsqrtf(s2 * (1.f / CH) - mean * mean + 1e-5f);
        int t = t0 + i;
        int hw = hw0 + i, hh = hw >> 6, wc = hw & 63;
        int wh = hh >> 3, ii = hh & 7, ww = wc >> 3, jj = wc & 7;
        int r = ((b * 64 + wh * 8 + ww) << 6) + (ii << 3) + jj;
        #pragma unroll
        for (int k = 0; k < 8; k++) {
            int c = lane + 32 * k;
            float v = tx[c][i];
            g_xf_h[(size_t)t * CH + c] = __float2half(v);
            g_xnw_h[(size_t)r * CH + c] = __float2half((v - mean) * inv * gw[c] + gb[c]);
        }
    }
}

// ---------------- LayerNorm 2: one warp per token, no block sync ----------------
__global__ __launch_bounds__(256) void ln2_kernel(const float* __restrict__ gw,
                                                  const float* __restrict__ gb) {
    int lane = threadIdx.x & 31, w = threadIdx.x >> 5;
    int t = blockIdx.x * 8 + w;
    const float* src = g_xf2 + (size_t)t * CH + lane * 8;
    float4 v0 = *(const float4*)src;
    float4 v1 = *(const float4*)(src + 4);
    float s  = v0.x + v0.y + v0.z + v0.w + v1.x + v1.y + v1.z + v1.w;
    float s2 = v0.x*v0.x + v0.y*v0.y + v0.z*v0.z + v0.w*v0.w
             + v1.x*v1.x + v1.y*v1.y + v1.z*v1.z + v1.w*v1.w;
    #pragma unroll
    for (int o = 16; o; o >>= 1) { s += __shfl_xor_sync(~0u, s, o); s2 += __shfl_xor_sync(~0u, s2, o); }
    float mean = s * (1.f / CH);
    float inv = rsqrtf(s2 * (1.f / CH) - mean * mean + 1e-5f);
    int c0 = lane * 8;
    float4 gwv0 = *(const float4*)(gw + c0), gwv1 = *(const float4*)(gw + c0 + 4);
    float4 gbv0 = *(const float4*)(gb + c0), gbv1 = *(const float4*)(gb + c0 + 4);
    uint4 outv;
    outv.x = f2h2((v0.x - mean) * inv * gwv0.x + gbv0.x, (v0.y - mean) * inv * gwv0.y + gbv0.y);
    outv.y = f2h2((v0.z - mean) * inv * gwv0.z + gbv0.z, (v0.w - mean) * inv * gwv0.w + gbv0.w);
    outv.z = f2h2((v1.x - mean) * inv * gwv1.x + gbv1.x, (v1.y - mean) * inv * gwv1.y + gbv1.y);
    outv.w = f2h2((v1.z - mean) * inv * gwv1.z + gbv1.z, (v1.w - mean) * inv * gwv1.w + gbv1.w);
    *(uint4*)(g_ln2_h + (size_t)t * CH + c0) = outv;
}

// ---------------- tensor-core attention: one block per (win, head), 4 warps, f16 acc ----------------
__global__ __launch_bounds__(128) void attn_mma() {
    int win = blockIdx.x >> 3, head = blockIdx.x & 7;
    __shared__ __half sq[64 * 40], sk[64 * 40], sv[64 * 40];
    int tid = threadIdx.x, lane = tid & 31, w = tid >> 5;

    const __half* qb = g_q + (size_t)(win * NHEAD + head) * 2048;
    const __half* kb = g_k + (size_t)(win * NHEAD + head) * 2048;
    const __half* vb = g_v + (size_t)(win * NHEAD + head) * 2048;
    #pragma unroll
    for (int j = 0; j < 2; j++) {
        int ch = tid + (j << 7);
        int row = ch >> 2, cq = ch & 3;
        *(uint4*)&sq[row * 40 + cq * 8] = *(const uint4*)(qb + row * 32 + cq * 8);
        *(uint4*)&sk[row * 40 + cq * 8] = *(const uint4*)(kb + row * 32 + cq * 8);
        *(uint4*)&sv[row * 40 + cq * 8] = *(const uint4*)(vb + row * 32 + cq * 8);
    }
    __syncthreads();

    uint32_t bq = smem_u32(sq), bk = smem_u32(sk), bv = smem_u32(sv);
    int g = lane >> 2, tg = lane & 3;

    uint32_t aq[2][4];
    #pragma unroll
    for (int t = 0; t < 2; t++)
        ldsm4(aq[t], bq + (((16 * w + (lane & 15)) * 40 + t * 16 + (lane >> 4) * 8) << 1));

    uint32_t acch[8][2] = {};
    #pragma unroll
    for (int t = 0; t < 2; t++)
        #pragma unroll
        for (int u = 0; u < 4; u++) {
            uint32_t bf[4];
            ldsm4(bf, bk + (((16 * u + (lane & 15)) * 40 + t * 16 + (lane >> 4) * 8) << 1));
            mma16816h(acch[2 * u],     aq[t], bf[0], bf[2]);
            mma16816h(acch[2 * u + 1], aq[t], bf[1], bf[3]);
        }

    // unpack to f32, + bias (direct global loads, L2-resident table), softmax
    const float* bbg = g_bias + head * 4096;
    float acc[8][4];
    int r0 = 16 * w + g, r1 = r0 + 8;
    float mx0 = -1e30f, mx1 = -1e30f;
    #pragma unroll
    for (int s = 0; s < 8; s++) {
        __half2 h0 = *(__half2*)&acch[s][0];
        __half2 h1 = *(__half2*)&acch[s][1];
        float2 b0 = __ldg((const float2*)&bbg[r0 * 64 + 8 * s + tg * 2]);
        float2 b1 = __ldg((const float2*)&bbg[r1 * 64 + 8 * s + tg * 2]);
        acc[s][0] = __low2float(h0)  + b0.x;
        acc[s][1] = __high2float(h0) + b0.y;
        acc[s][2] = __low2float(h1)  + b1.x;
        acc[s][3] = __high2float(h1) + b1.y;
        mx0 = fmaxf(mx0, fmaxf(acc[s][0], acc[s][1]));
        mx1 = fmaxf(mx1, fmaxf(acc[s][2], acc[s][3]));
    }
    mx0 = fmaxf(mx0, __shfl_xor_sync(~0u, mx0, 1)); mx0 = fmaxf(mx0, __shfl_xor_sync(~0u, mx0, 2));
    mx1 = fmaxf(mx1, __shfl_xor_sync(~0u, mx1, 1)); mx1 = fmaxf(mx1, __shfl_xor_sync(~0u, mx1, 2));
    float sm0 = 0.f, sm1 = 0.f;
    #pragma unroll
    for (int s = 0; s < 8; s++) {
        acc[s][0] = __expf(acc[s][0] - mx0); acc[s][1] = __expf(acc[s][1] - mx0);
        acc[s][2] = __expf(acc[s][2] - mx1); acc[s][3] = __expf(acc[s][3] - mx1);
        sm0 += acc[s][0] + acc[s][1];
        sm1 += acc[s][2] + acc[s][3];
    }
    sm0 += __shfl_xor_sync(~0u, sm0, 1); sm0 += __shfl_xor_sync(~0u, sm0, 2);
    sm1 += __shfl_xor_sync(~0u, sm1, 1); sm1 += __shfl_xor_sync(~0u, sm1, 2);
    float iv0 = 1.f / sm0, iv1 = 1.f / sm1;
    uint32_t ap[4][4];
    #pragma unroll
    for (int t = 0; t < 4; t++) {
        ap[t][0] = f2h2(acc[2*t][0]*iv0,   acc[2*t][1]*iv0);
        ap[t][1] = f2h2(acc[2*t][2]*iv1,   acc[2*t][3]*iv1);
        ap[t][2] = f2h2(acc[2*t+1][0]*iv0, acc[2*t+1][1]*iv0);
        ap[t][3] = f2h2(acc[2*t+1][2]*iv1, acc[2*t+1][3]*iv1);
    }

    uint32_t oacch[4][2] = {};
    #pragma unroll
    for (int t = 0; t < 4; t++)
        #pragma unroll
        for (int np = 0; np < 2; np++) {
            uint32_t bf[4];
            ldsm4t(bf, bv + (((16 * t + (lane & 15)) * 40 + np * 16 + (lane >> 4) * 8) << 1));
            mma16816h(oacch[2 * np],     ap[t], bf[0], bf[1]);
            mma16816h(oacch[2 * np + 1], ap[t], bf[2], bf[3]);
        }

    __half* ob = g_att_h + ((size_t)win * 64) * 256 + head * 32;
    #pragma unroll
    for (int n = 0; n < 4; n++) {
        *(uint32_t*)&ob[(size_t)r0 * 256 + 8 * n + tg * 2] = oacch[n][0];
        *(uint32_t*)&ob[(size_t)r1 * 256 + 8 * n + tg * 2] = oacch[n][1];
    }
}

// ---------------- depthwise 9x9 conv + unfold, half2 datapath; accumulates into g_att_h ----------------
__global__ __launch_bounds__(256) void gaze_conv_kernel(const float* __restrict__ gw,
                                                        const float* __restrict__ gb) {
    int bidx = blockIdx.x;                 // 16*64*8
    int cc = bidx & 7;
    int tile = (bidx >> 3) & 63;
    int b = bidx >> 9;
    int tr = (tile >> 3) << 3;
    int tc = (tile & 7) << 3;
    int ch0 = cc << 5;

    __shared__ __half2 sin_h[16][16][16];  // 16 KB
    __shared__ __half2 swt_h[81][16];      // 5.2 KB
    int tid = threadIdx.x;

    for (int i = tid; i < 81 * 16; i += 256) {
        int tap = i >> 4, c2 = i & 15;
        swt_h[tap][c2] = __floats2half2_rn(gw[tap * CH + ch0 + 2 * c2],
                                           gw[tap * CH + ch0 + 2 * c2 + 1]);
    }
    for (int i = tid; i < 16 * 16 * 16; i += 256) {
        int c2 = i & 15, px = (i >> 4) & 15, py = i >> 8;
        int R = tr - 4 + py, Cc = tc - 4 + px;
        __half2 v = __floats2half2_rn(0.f, 0.f);
        if (R >= 0 && R < 64 && Cc >= 0 && Cc < 64)
            v = *(const __half2*)&g_img_h[(((size_t)((b << 6) + R) << 6) + Cc) * CH + ch0 + 2 * c2];
        sin_h[py][px][c2] = v;
    }
    __syncthreads();

    int c2 = tid & 15, px = (tid >> 4) & 7, pyh = tid >> 7;
    __half2 acc[4];
    #pragma unroll
    for (int i = 0; i < 4; i++) acc[i] = __floats2half2_rn(0.f, 0.f);
    #pragma unroll
    for (int dx = 0; dx < 9; dx++) {
        __half2 col[12];
        #pragma unroll
        for (int ry = 0; ry < 12; ry++) col[ry] = sin_h[pyh * 4 + ry][px + dx][c2];
        #pragma unroll
        for (int dy = 0; dy < 9; dy++) {
            __half2 wv = swt_h[dy * 9 + dx][c2];
            #pragma unroll
            for (int py = 0; py < 4; py++) acc[py] = __hfma2(col[py + dy], wv, acc[py]);
        }
    }
    __half2 bias2 = __floats2half2_rn(gb[ch0 + 2 * c2], gb[ch0 + 2 * c2 + 1]);
    #pragma unroll
    for (int py = 0; py < 4; py++) {
        int R = tr + pyh * 4 + py, Cc = tc + px;
        int wh = R & 7, ii = R >> 3, ww = Cc & 7, jj = Cc >> 3;
        int r = ((b * 64 + wh * 8 + ww) << 6) + (ii << 3) + jj;
        size_t o = (size_t)r * CH + ch0 + 2 * c2;
        __half2 old = *(__half2*)&g_att_h[o];
        *(__half2*)&g_att_h[o] = __hadd2(old, __hadd2(acc[py], bias2));
    }
}

// ---------------- host launch ----------------
extern "C" void kernel_launch(void* const* d_in, const int* in_sizes, int n_in,
                              void* d_out, int out_size) {
    int off = (n_in >= 18) ? 2 : 0;
    const float* x       = (const float*)d_in[off + 0];
    const float* norm1_g = (const float*)d_in[off + 1];
    const float* norm1_b = (const float*)d_in[off + 2];
    const float* qkv_w   = (const float*)d_in[off + 3];
    const float* qkv_b   = (const float*)d_in[off + 4];
    const float* rpb     = (const float*)d_in[off + 5];
    const float* proj_w  = (const float*)d_in[off + 6];
    const float* proj_b  = (const float*)d_in[off + 7];
    const float* gaze_w  = (const float*)d_in[off + 8];
    const float* gaze_b  = (const float*)d_in[off + 9];
    const float* norm2_g = (const float*)d_in[off + 10];
    const float* norm2_b = (const float*)d_in[off + 11];
    const float* fc1_w   = (const float*)d_in[off + 12];
    const float* fc1_b   = (const float*)d_in[off + 13];
    const float* fc2_w   = (const float*)d_in[off + 14];
    const float* fc2_b   = (const float*)d_in[off + 15];

    __half *pw_qkv, *pw_proj, *pw_fc1, *pw_fc2;
    __half *p_xnw, *p_atth, *p_ln2, *p_h1;
    cudaGetSymbolAddress((void**)&pw_qkv, w_qkv);
    cudaGetSymbolAddress((void**)&pw_proj, w_proj);
    cudaGetSymbolAddress((void**)&pw_fc1, w_fc1);
    cudaGetSymbolAddress((void**)&pw_fc2, w_fc2);
    cudaGetSymbolAddress((void**)&p_xnw, g_xnw_h);
    cudaGetSymbolAddress((void**)&p_atth, g_att_h);
    cudaGetSymbolAddress((void**)&p_ln2, g_ln2_h);
    cudaGetSymbolAddress((void**)&p_h1,  g_h1_h);

    cudaFuncSetAttribute((const void*)hgemm<EpiQKV>,  cudaFuncAttributeMaxDynamicSharedMemorySize, SMEM_DYN);
    cudaFuncSetAttribute((const void*)hgemm<EpiProj>, cudaFuncAttributeMaxDynamicSharedMemorySize, SMEM_DYN);
    cudaFuncSetAttribute((const void*)hgemm<EpiFC1>,  cudaFuncAttributeMaxDynamicSharedMemorySize, SMEM_DYN);
    cudaFuncSetAttribute((const void*)hgemm<EpiFC2>,  cudaFuncAttributeMaxDynamicSharedMemorySize, SMEM_DYN);

    cvt_all<<<768, 256>>>(qkv_w, proj_w, fc1_w, fc2_w);
    bias_kernel<<<128, 256>>>(rpb);
    ln1_kernel<<<2048, 256>>>(x, norm1_g, norm1_b);
    hgemm<EpiQKV><<<dim3(6, 512), 256, SMEM_DYN>>>(p_xnw, pw_qkv, 256, EpiQKV{qkv_b});
    attn_mma<<<8192, 128>>>();
    gaze_conv_kernel<<<8192, 256>>>(gaze_w, gaze_b);
    hgemm<EpiProj><<<dim3(2, 512), 256, SMEM_DYN>>>(p_atth, pw_proj, 256, EpiProj{proj_b});
    ln2_kernel<<<8192, 256>>>(norm2_g, norm2_b);
    hgemm<EpiFC1><<<dim3(8, 512), 256, SMEM_DYN>>>(p_ln2, pw_fc1, 256, EpiFC1{fc1_b});
    hgemm<EpiFC2><<<dim3(2, 512), 256, SMEM_DYN>>>(p_h1, pw_fc2, 1024, EpiFC2{fc2_b, (float*)d_out});
}

// round 16
// speedup vs baseline: 1.2675x; 1.0035x over previous
#include <cuda_runtime.h>
#include <cuda_fp16.h>
#include <math.h>
#include <stdint.h>

#define BATCH   16
#define CH      256
#define TOKENS  (BATCH*64*64)      // 65536
#define HID     1024
#define NHEAD   8
#define NTOK    64

// ---------------- scratch (device globals; allocation-free) ----------------
__device__ float  g_xf2 [TOKENS*CH];   // after proj residual, token-major (fp32)
__device__ float  g_bias[NHEAD*NTOK*NTOK];

__device__ __half g_xf_h [TOKENS*CH];  // shortcut, token-major (fp16)
__device__ __half g_xnw_h[TOKENS*CH];  // LN1 out, windowed
__device__ __half g_q   [TOKENS*CH];   // [win][head][pos][hd], pre-scaled
__device__ __half g_k   [TOKENS*CH];
__device__ __half g_v   [TOKENS*CH];
__device__ __half g_img_h[TOKENS*CH];  // folded image NHWC
__device__ __half g_att_h[TOKENS*CH];  // attn out; gaze accumulates in-place
__device__ __half g_ln2_h[TOKENS*CH];
__device__ __half g_h1_h [TOKENS*HID];

__device__ __half w_qkv [768*256];
__device__ __half w_proj[256*256];
__device__ __half w_fc1 [1024*256];
__device__ __half w_fc2 [256*1024];

// ============================ helpers ============================
__device__ __forceinline__ uint32_t smem_u32(const void* p) {
    uint32_t a;
    asm("{ .reg .u64 t; cvta.to.shared.u64 t, %1; cvt.u32.u64 %0, t; }" : "=r"(a) : "l"(p));
    return a;
}
__device__ __forceinline__ uint32_t f2h2(float a, float b) {
    __half2 h = __floats2half2_rn(a, b);
    return *reinterpret_cast<uint32_t*>(&h);
}
__device__ __forceinline__ void ldsm4(uint32_t (&r)[4], uint32_t addr) {
    asm volatile("ldmatrix.sync.aligned.m8n8.x4.shared.b16 {%0,%1,%2,%3}, [%4];"
                 : "=r"(r[0]), "=r"(r[1]), "=r"(r[2]), "=r"(r[3]) : "r"(addr));
}
__device__ __forceinline__ void ldsm4t(uint32_t (&r)[4], uint32_t addr) {
    asm volatile("ldmatrix.sync.aligned.m8n8.x4.trans.shared.b16 {%0,%1,%2,%3}, [%4];"
                 : "=r"(r[0]), "=r"(r[1]), "=r"(r[2]), "=r"(r[3]) : "r"(addr));
}
__device__ __forceinline__ void mma16816h(uint32_t* d, const uint32_t* a, uint32_t b0, uint32_t b1) {
    asm volatile("mma.sync.aligned.m16n8k16.row.col.f16.f16.f16.f16 "
                 "{%0,%1},{%2,%3,%4,%5},{%6,%7},{%0,%1};"
                 : "+r"(d[0]), "+r"(d[1])
                 : "r"(a[0]), "r"(a[1]), "r"(a[2]), "r"(a[3]), "r"(b0), "r"(b1));
}
#define CP_A16(dst, src) asm volatile("cp.async.cg.shared.global [%0], [%1], 16;" :: "r"(dst), "l"(src))
#define CP_COMMIT()      asm volatile("cp.async.commit_group;")
#define CP_WAIT(n)       asm volatile("cp.async.wait_group %0;" :: "n"(n))

// ============================ fp16 GEMM, cp.async 3-stage, f16 accumulators ============================
// C[m][n] = sum_k A[m][k]*W[n][k].  BM=BN=128, BK=32, 256 thr (2x4 warps), warp tile 64x32.
#define LDSTR 40
#define SSZ   (128*LDSTR)                 // halves per tensor per stage
#define SMEM_DYN (3*2*SSZ*2)              // 61440 bytes

template <class Epi>
__global__ __launch_bounds__(256, 2) void hgemm(const __half* __restrict__ A,
                                                const __half* __restrict__ W,
                                                int K, Epi epi) {
    extern __shared__ __half sm[];
    int tid = threadIdx.x, lane = tid & 31, wid = tid >> 5;
    int wm = wid >> 2, wn = wid & 3;
    int bm = blockIdx.y << 7, bn = blockIdx.x << 7;
    int NC = K >> 5;
    uint32_t smb = smem_u32(sm);

    auto issue = [&](int st, int ic) {
        int k0 = ic << 5;
        uint32_t sb = smb + st * (2 * SSZ) * 2;
        #pragma unroll
        for (int j = 0; j < 2; j++) {
            int ch = tid + (j << 8);
            int row = ch >> 2, cq = ch & 3;
            uint32_t da = sb + (row * LDSTR + cq * 8) * 2;
            CP_A16(da, A + (size_t)(bm + row) * K + k0 + cq * 8);
            CP_A16(da + SSZ * 2, W + (size_t)(bn + row) * K + k0 + cq * 8);
        }
        CP_COMMIT();
    };

    issue(0, 0); issue(1, 1);
    uint32_t acch[4][4][2] = {};
    for (int ic = 0; ic < NC; ic++) {
        if (ic + 1 < NC) CP_WAIT(1); else CP_WAIT(0);
        __syncthreads();
        if (ic + 2 < NC) issue((ic + 2) % 3, ic + 2);
        uint32_t baseA = smb + (ic % 3) * (2 * SSZ) * 2;
        uint32_t baseB = baseA + SSZ * 2;
        #pragma unroll
        for (int ks = 0; ks < 2; ks++) {
            uint32_t af[4][4], bf[2][4];
            #pragma unroll
            for (int mt = 0; mt < 4; mt++)
                ldsm4(af[mt], baseA + (((wm*64 + mt*16 + (lane & 15)) * LDSTR + ks*16 + (lane >> 4)*8) << 1));
            #pragma unroll
            for (int bt = 0; bt < 2; bt++)
                ldsm4(bf[bt], baseB + (((wn*32 + bt*16 + (lane & 15)) * LDSTR + ks*16 + (lane >> 4)*8) << 1));
            #pragma unroll
            for (int mt = 0; mt < 4; mt++)
                #pragma unroll
                for (int nt = 0; nt < 4; nt++)
                    mma16816h(acch[mt][nt], af[mt], bf[nt>>1][nt&1], bf[nt>>1][(nt&1)+2]);
        }
    }
    int g = lane >> 2, tg = lane & 3;

    if constexpr (Epi::STAGED) {
        // FC2: val = acc + bias + xf2, then NCHW-coalesced write via smem stage (2 half-tiles)
        float* stg = (float*)sm;
        int b = bm >> 12, hw0 = bm & 4095;
        for (int p = 0; p < 2; p++) {
            __syncthreads();
            if (wm == p) {
                #pragma unroll
                for (int mt = 0; mt < 4; mt++) {
                    int lr = mt * 16 + g;
                    size_t gr0 = (size_t)(bm + p * 64 + lr) * CH;
                    size_t gr1 = gr0 + 8 * CH;
                    #pragma unroll
                    for (int nt = 0; nt < 4; nt++) {
                        int c = wn * 32 + nt * 8 + tg * 2;
                        __half2 h0 = *(__half2*)&acch[mt][nt][0];
                        __half2 h1 = *(__half2*)&acch[mt][nt][1];
                        float2 x0 = *(const float2*)&g_xf2[gr0 + bn + c];
                        float2 x1 = *(const float2*)&g_xf2[gr1 + bn + c];
                        stg[lr * 132 + c]           = __low2float(h0)  + epi.bias[bn + c]     + x0.x;
                        stg[lr * 132 + c + 1]       = __high2float(h0) + epi.bias[bn + c + 1] + x0.y;
                        stg[(lr + 8) * 132 + c]     = __low2float(h1)  + epi.bias[bn + c]     + x1.x;
                        stg[(lr + 8) * 132 + c + 1] = __high2float(h1) + epi.bias[bn + c + 1] + x1.y;
                    }
                }
            }
            __syncthreads();
            #pragma unroll 1
            for (int i = 0; i < 32; i++) {
                int idx = tid + (i << 8);
                int row = idx & 63, c = idx >> 6;
                epi.out[((size_t)(b * CH + bn + c) << 12) + hw0 + p * 64 + row] = stg[row * 132 + c];
            }
        }
    } else {
        #pragma unroll
        for (int mt = 0; mt < 4; mt++) {
            int M0 = bm + wm * 64 + mt * 16;
            #pragma unroll
            for (int nt = 0; nt < 4; nt++) {
                int N0 = bn + wn * 32 + nt * 8 + tg * 2;
                __half2 h0 = *(__half2*)&acch[mt][nt][0];
                __half2 h1 = *(__half2*)&acch[mt][nt][1];
                epi.pair(M0 + g,     N0, __low2float(h0), __high2float(h0));
                epi.pair(M0 + g + 8, N0, __low2float(h1), __high2float(h1));
            }
        }
    }
}

// ============================ epilogues (pair interface: c even) ============================
struct EpiQKV {
    const float* bias;
    static constexpr bool STAGED = false;
    __device__ void pair(int r, int c, float a0, float a1) const {
        float va = a0 + bias[c], vb = a1 + bias[c + 1];
        int part = c >> 8, head = (c >> 5) & 7, d = c & 31;
        int win = r >> 6, pos = r & 63;
        size_t o = (size_t)(win * NHEAD + head) * 2048 + pos * 32 + d;
        if (part == 0)      *(uint32_t*)&g_q[o] = f2h2(va * 4.0f, vb * 4.0f);
        else if (part == 1) *(uint32_t*)&g_k[o] = f2h2(va, vb);
        else {
            uint32_t hv = f2h2(va, vb);
            *(uint32_t*)&g_v[o] = hv;
            int b = win >> 6, wh = (win >> 3) & 7, ww = win & 7;
            int ii = pos >> 3, jj = pos & 7;
            int R = ii * 8 + wh, Cc = jj * 8 + ww;
            *(uint32_t*)&g_img_h[(((size_t)((b << 6) + R) << 6) + Cc) * CH + (c - 512)] = hv;
        }
    }
};
struct EpiProj {
    const float* bias;
    static constexpr bool STAGED = false;
    __device__ void pair(int r, int c, float a0, float a1) const {
        int win = r >> 6, pos = r & 63;
        int b = win >> 6, wh = (win >> 3) & 7, ww = win & 7;
        int ii = pos >> 3, jj = pos & 7;
        int t = (b << 12) + ((wh * 8 + ii) << 6) + ww * 8 + jj;
        size_t o = (size_t)t * CH + c;
        __half2 xf = *(const __half2*)&g_xf_h[o];
        float2 res = make_float2(__low2float(xf) + a0 + bias[c],
                                 __high2float(xf) + a1 + bias[c + 1]);
        *(float2*)&g_xf2[o] = res;
    }
};
struct EpiFC1 {
    const float* bias;
    static constexpr bool STAGED = false;
    __device__ void pair(int r, int c, float a0, float a1) const {
        float x0 = a0 + bias[c], x1 = a1 + bias[c + 1];
        float g0 = 0.5f * x0 * (1.0f + erff(x0 * 0.70710678118654752f));
        float g1 = 0.5f * x1 * (1.0f + erff(x1 * 0.70710678118654752f));
        *(uint32_t*)&g_h1_h[(size_t)r * HID + c] = f2h2(g0, g1);
    }
};
struct EpiFC2 {
    const float* bias;
    float* out;
    static constexpr bool STAGED = true;
    __device__ void pair(int, int, float, float) const {}
};

// ---------------- all weights fp32 -> fp16, one vectorized launch ----------------
__global__ __launch_bounds__(256) void cvt_all(const float* __restrict__ qkv,
                                               const float* __restrict__ proj,
                                               const float* __restrict__ fc1,
                                               const float* __restrict__ fc2) {
    int i4 = blockIdx.x * 256 + threadIdx.x;    // 196608 float4 units
    int i = i4 * 4;
    const float* s;
    __half* d;
    if (i < 196608)      { s = qkv  + i;          d = w_qkv  + i; }
    else if (i < 262144) { s = proj + (i-196608); d = w_proj + (i-196608); }
    else if (i < 524288) { s = fc1  + (i-262144); d = w_fc1  + (i-262144); }
    else                 { s = fc2  + (i-524288); d = w_fc2  + (i-524288); }
    float4 v = *(const float4*)s;
    uint2 h;
    h.x = f2h2(v.x, v.y);
    h.y = f2h2(v.z, v.w);
    *(uint2*)d = h;
}

// ---------------- relative position bias prep ----------------
__global__ void bias_kernel(const float* __restrict__ rpb) {
    int idx = blockIdx.x * 256 + threadIdx.x;
    int h_ = idx >> 12, n = (idx >> 6) & 63, m = idx & 63;
    int di = (n >> 3) - (m >> 3) + 7;
    int dj = (n & 7) - (m & 7) + 7;
    g_bias[idx] = rpb[(di * 15 + dj) * NHEAD + h_];
}

// ---------------- LayerNorm 1 (float4 global loads) ----------------
__global__ __launch_bounds__(256) void ln1_kernel(const float* __restrict__ x,
                                                  const float* __restrict__ gw,
                                                  const float* __restrict__ gb) {
    __shared__ float tx[256][33];
    int t0 = blockIdx.x * 32;
    int b = t0 >> 12, hw0 = t0 & 4095;
    int tid = threadIdx.x;
    // load 32 tokens x 256 channels via float4: idx over 2048 quads
    #pragma unroll
    for (int j = 0; j < 8; j++) {
        int idx = j * 256 + tid;
        int c = idx >> 3, i4 = idx & 7;
        float4 v = *(const float4*)&x[((size_t)(b * CH + c) << 12) + hw0 + i4 * 4];
        tx[c][i4 * 4 + 0] = v.x;
        tx[c][i4 * 4 + 1] = v.y;
        tx[c][i4 * 4 + 2] = v.z;
        tx[c][i4 * 4 + 3] = v.w;
    }
    __syncthreads();
    int lane = tid & 31, w = tid >> 5;
    #pragma unroll
    for (int q = 0; q < 4; q++) {
        int i = w * 4 + q;
        float s = 0.f, s2 = 0.f;
        #pragma unroll
        for (int k = 0; k < 8; k++) { float v = tx[lane + 32 * k][i]; s += v; s2 += v * v; }
        #pragma unroll
        for (int o = 16; o; o >>= 1) { s += __shfl_xor_sync(~0u, s, o); s2 += __shfl_xor_sync(~0u, s2, o); }
        float mean = s * (1.f / CH);
        float inv = rsqrtf(s2 * (1.f / CH) - mean * mean + 1e-5f);
        int t = t0 + i;
        int hw = hw0 + i, hh = hw >> 6, wc = hw & 63;
        int wh = hh >> 3, ii = hh & 7, ww = wc >> 3, jj = wc & 7;
        int r = ((b * 64 + wh * 8 + ww) << 6) + (ii << 3) + jj;
        #pragma unroll
        for (int k = 0; k < 8; k++) {
            int c = lane + 32 * k;
            float v = tx[c][i];
            g_xf_h[(size_t)t * CH + c] = __float2half(v);
            g_xnw_h[(size_t)r * CH + c] = __float2half((v - mean) * inv * gw[c] + gb[c]);
        }
    }
}

// ---------------- LayerNorm 2: one warp per token, no block sync ----------------
__global__ __launch_bounds__(256) void ln2_kernel(const float* __restrict__ gw,
                                                  const float* __restrict__ gb) {
    int lane = threadIdx.x & 31, w = threadIdx.x >> 5;
    int t = blockIdx.x * 8 + w;
    const float* src = g_xf2 + (size_t)t * CH + lane * 8;
    float4 v0 = *(const float4*)src;
    float4 v1 = *(const float4*)(src + 4);
    float s  = v0.x + v0.y + v0.z + v0.w + v1.x + v1.y + v1.z + v1.w;
    float s2 = v0.x*v0.x + v0.y*v0.y + v0.z*v0.z + v0.w*v0.w
             + v1.x*v1.x + v1.y*v1.y + v1.z*v1.z + v1.w*v1.w;
    #pragma unroll
    for (int o = 16; o; o >>= 1) { s += __shfl_xor_sync(~0u, s, o); s2 += __shfl_xor_sync(~0u, s2, o); }
    float mean = s * (1.f / CH);
    float inv = rsqrtf(s2 * (1.f / CH) - mean * mean + 1e-5f);
    int c0 = lane * 8;
    float4 gwv0 = *(const float4*)(gw + c0), gwv1 = *(const float4*)(gw + c0 + 4);
    float4 gbv0 = *(const float4*)(gb + c0), gbv1 = *(const float4*)(gb + c0 + 4);
    uint4 outv;
    outv.x = f2h2((v0.x - mean) * inv * gwv0.x + gbv0.x, (v0.y - mean) * inv * gwv0.y + gbv0.y);
    outv.y = f2h2((v0.z - mean) * inv * gwv0.z + gbv0.z, (v0.w - mean) * inv * gwv0.w + gbv0.w);
    outv.z = f2h2((v1.x - mean) * inv * gwv1.x + gbv1.x, (v1.y - mean) * inv * gwv1.y + gbv1.y);
    outv.w = f2h2((v1.z - mean) * inv * gwv1.z + gbv1.z, (v1.w - mean) * inv * gwv1.w + gbv1.w);
    *(uint4*)(g_ln2_h + (size_t)t * CH + c0) = outv;
}

// ---------------- tensor-core attention: one block per (win, head), 4 warps, f16 acc ----------------
__global__ __launch_bounds__(128) void attn_mma() {
    int win = blockIdx.x >> 3, head = blockIdx.x & 7;
    __shared__ __half sq[64 * 40], sk[64 * 40], sv[64 * 40];
    int tid = threadIdx.x, lane = tid & 31, w = tid >> 5;

    const __half* qb = g_q + (size_t)(win * NHEAD + head) * 2048;
    const __half* kb = g_k + (size_t)(win * NHEAD + head) * 2048;
    const __half* vb = g_v + (size_t)(win * NHEAD + head) * 2048;
    #pragma unroll
    for (int j = 0; j < 2; j++) {
        int ch = tid + (j << 7);
        int row = ch >> 2, cq = ch & 3;
        *(uint4*)&sq[row * 40 + cq * 8] = *(const uint4*)(qb + row * 32 + cq * 8);
        *(uint4*)&sk[row * 40 + cq * 8] = *(const uint4*)(kb + row * 32 + cq * 8);
        *(uint4*)&sv[row * 40 + cq * 8] = *(const uint4*)(vb + row * 32 + cq * 8);
    }
    __syncthreads();

    uint32_t bq = smem_u32(sq), bk = smem_u32(sk), bv = smem_u32(sv);
    int g = lane >> 2, tg = lane & 3;

    uint32_t aq[2][4];
    #pragma unroll
    for (int t = 0; t < 2; t++)
        ldsm4(aq[t], bq + (((16 * w + (lane & 15)) * 40 + t * 16 + (lane >> 4) * 8) << 1));

    uint32_t acch[8][2] = {};
    #pragma unroll
    for (int t = 0; t < 2; t++)
        #pragma unroll
        for (int u = 0; u < 4; u++) {
            uint32_t bf[4];
            ldsm4(bf, bk + (((16 * u + (lane & 15)) * 40 + t * 16 + (lane >> 4) * 8) << 1));
            mma16816h(acch[2 * u],     aq[t], bf[0], bf[2]);
            mma16816h(acch[2 * u + 1], aq[t], bf[1], bf[3]);
        }

    const float* bbg = g_bias + head * 4096;
    float acc[8][4];
    int r0 = 16 * w + g, r1 = r0 + 8;
    float mx0 = -1e30f, mx1 = -1e30f;
    #pragma unroll
    for (int s = 0; s < 8; s++) {
        __half2 h0 = *(__half2*)&acch[s][0];
        __half2 h1 = *(__half2*)&acch[s][1];
        float2 b0 = __ldg((const float2*)&bbg[r0 * 64 + 8 * s + tg * 2]);
        float2 b1 = __ldg((const float2*)&bbg[r1 * 64 + 8 * s + tg * 2]);
        acc[s][0] = __low2float(h0)  + b0.x;
        acc[s][1] = __high2float(h0) + b0.y;
        acc[s][2] = __low2float(h1)  + b1.x;
        acc[s][3] = __high2float(h1) + b1.y;
        mx0 = fmaxf(mx0, fmaxf(acc[s][0], acc[s][1]));
        mx1 = fmaxf(mx1, fmaxf(acc[s][2], acc[s][3]));
    }
    mx0 = fmaxf(mx0, __shfl_xor_sync(~0u, mx0, 1)); mx0 = fmaxf(mx0, __shfl_xor_sync(~0u, mx0, 2));
    mx1 = fmaxf(mx1, __shfl_xor_sync(~0u, mx1, 1)); mx1 = fmaxf(mx1, __shfl_xor_sync(~0u, mx1, 2));
    float sm0 = 0.f, sm1 = 0.f;
    #pragma unroll
    for (int s = 0; s < 8; s++) {
        acc[s][0] = __expf(acc[s][0] - mx0); acc[s][1] = __expf(acc[s][1] - mx0);
        acc[s][2] = __expf(acc[s][2] - mx1); acc[s][3] = __expf(acc[s][3] - mx1);
        sm0 += acc[s][0] + acc[s][1];
        sm1 += acc[s][2] + acc[s][3];
    }
    sm0 += __shfl_xor_sync(~0u, sm0, 1); sm0 += __shfl_xor_sync(~0u, sm0, 2);
    sm1 += __shfl_xor_sync(~0u, sm1, 1); sm1 += __shfl_xor_sync(~0u, sm1, 2);
    float iv0 = 1.f / sm0, iv1 = 1.f / sm1;
    uint32_t ap[4][4];
    #pragma unroll
    for (int t = 0; t < 4; t++) {
        ap[t][0] = f2h2(acc[2*t][0]*iv0,   acc[2*t][1]*iv0);
        ap[t][1] = f2h2(acc[2*t][2]*iv1,   acc[2*t][3]*iv1);
        ap[t][2] = f2h2(acc[2*t+1][0]*iv0, acc[2*t+1][1]*iv0);
        ap[t][3] = f2h2(acc[2*t+1][2]*iv1, acc[2*t+1][3]*iv1);
    }

    uint32_t oacch[4][2] = {};
    #pragma unroll
    for (int t = 0; t < 4; t++)
        #pragma unroll
        for (int np = 0; np < 2; np++) {
            uint32_t bf[4];
            ldsm4t(bf, bv + (((16 * t + (lane & 15)) * 40 + np * 16 + (lane >> 4) * 8) << 1));
            mma16816h(oacch[2 * np],     ap[t], bf[0], bf[1]);
            mma16816h(oacch[2 * np + 1], ap[t], bf[2], bf[3]);
        }

    __half* ob = g_att_h + ((size_t)win * 64) * 256 + head * 32;
    #pragma unroll
    for (int n = 0; n < 4; n++) {
        *(uint32_t*)&ob[(size_t)r0 * 256 + 8 * n + tg * 2] = oacch[n][0];
        *(uint32_t*)&ob[(size_t)r1 * 256 + 8 * n + tg * 2] = oacch[n][1];
    }
}

// ---------------- depthwise 9x9 conv + unfold, half2 datapath; accumulates into g_att_h ----------------
__global__ __launch_bounds__(256) void gaze_conv_kernel(const float* __restrict__ gw,
                                                        const float* __restrict__ gb) {
    int bidx = blockIdx.x;                 // 16*64*8
    int cc = bidx & 7;
    int tile = (bidx >> 3) & 63;
    int b = bidx >> 9;
    int tr = (tile >> 3) << 3;
    int tc = (tile & 7) << 3;
    int ch0 = cc << 5;

    __shared__ __half2 sin_h[16][16][16];  // 16 KB
    __shared__ __half2 swt_h[81][16];      // 5.2 KB
    int tid = threadIdx.x;

    for (int i = tid; i < 81 * 16; i += 256) {
        int tap = i >> 4, c2 = i & 15;
        swt_h[tap][c2] = __floats2half2_rn(gw[tap * CH + ch0 + 2 * c2],
                                           gw[tap * CH + ch0 + 2 * c2 + 1]);
    }
    for (int i = tid; i < 16 * 16 * 16; i += 256) {
        int c2 = i & 15, px = (i >> 4) & 15, py = i >> 8;
        int R = tr - 4 + py, Cc = tc - 4 + px;
        __half2 v = __floats2half2_rn(0.f, 0.f);
        if (R >= 0 && R < 64 && Cc >= 0 && Cc < 64)
            v = *(const __half2*)&g_img_h[(((size_t)((b << 6) + R) << 6) + Cc) * CH + ch0 + 2 * c2];
        sin_h[py][px][c2] = v;
    }
    __syncthreads();

    int c2 = tid & 15, px = (tid >> 4) & 7, pyh = tid >> 7;
    __half2 acc[4];
    #pragma unroll
    for (int i = 0; i < 4; i++) acc[i] = __floats2half2_rn(0.f, 0.f);
    #pragma unroll
    for (int dx = 0; dx < 9; dx++) {
        __half2 col[12];
        #pragma unroll
        for (int ry = 0; ry < 12; ry++) col[ry] = sin_h[pyh * 4 + ry][px + dx][c2];
        #pragma unroll
        for (int dy = 0; dy < 9; dy++) {
            __half2 wv = swt_h[dy * 9 + dx][c2];
            #pragma unroll
            for (int py = 0; py < 4; py++) acc[py] = __hfma2(col[py + dy], wv, acc[py]);
        }
    }
    __half2 bias2 = __floats2half2_rn(gb[ch0 + 2 * c2], gb[ch0 + 2 * c2 + 1]);
    #pragma unroll
    for (int py = 0; py < 4; py++) {
        int R = tr + pyh * 4 + py, Cc = tc + px;
        int wh = R & 7, ii = R >> 3, ww = Cc & 7, jj = Cc >> 3;
        int r = ((b * 64 + wh * 8 + ww) << 6) + (ii << 3) + jj;
        size_t o = (size_t)r * CH + ch0 + 2 * c2;
        __half2 old = *(__half2*)&g_att_h[o];
        *(__half2*)&g_att_h[o] = __hadd2(old, __hadd2(acc[py], bias2));
    }
}

// ---------------- host launch ----------------
extern "C" void kernel_launch(void* const* d_in, const int* in_sizes, int n_in,
                              void* d_out, int out_size) {
    int off = (n_in >= 18) ? 2 : 0;
    const float* x       = (const float*)d_in[off + 0];
    const float* norm1_g = (const float*)d_in[off + 1];
    const float* norm1_b = (const float*)d_in[off + 2];
    const float* qkv_w   = (const float*)d_in[off + 3];
    const float* qkv_b   = (const float*)d_in[off + 4];
    const float* rpb     = (const float*)d_in[off + 5];
    const float* proj_w  = (const float*)d_in[off + 6];
    const float* proj_b  = (const float*)d_in[off + 7];
    const float* gaze_w  = (const float*)d_in[off + 8];
    const float* gaze_b  = (const float*)d_in[off + 9];
    const float* norm2_g = (const float*)d_in[off + 10];
    const float* norm2_b = (const float*)d_in[off + 11];
    const float* fc1_w   = (const float*)d_in[off + 12];
    const float* fc1_b   = (const float*)d_in[off + 13];
    const float* fc2_w   = (const float*)d_in[off + 14];
    const float* fc2_b   = (const float*)d_in[off + 15];

    __half *pw_qkv, *pw_proj, *pw_fc1, *pw_fc2;
    __half *p_xnw, *p_atth, *p_ln2, *p_h1;
    cudaGetSymbolAddress((void**)&pw_qkv, w_qkv);
    cudaGetSymbolAddress((void**)&pw_proj, w_proj);
    cudaGetSymbolAddress((void**)&pw_fc1, w_fc1);
    cudaGetSymbolAddress((void**)&pw_fc2, w_fc2);
    cudaGetSymbolAddress((void**)&p_xnw, g_xnw_h);
    cudaGetSymbolAddress((void**)&p_atth, g_att_h);
    cudaGetSymbolAddress((void**)&p_ln2, g_ln2_h);
    cudaGetSymbolAddress((void**)&p_h1,  g_h1_h);

    cudaFuncSetAttribute((const void*)hgemm<EpiQKV>,  cudaFuncAttributeMaxDynamicSharedMemorySize, SMEM_DYN);
    cudaFuncSetAttribute((const void*)hgemm<EpiProj>, cudaFuncAttributeMaxDynamicSharedMemorySize, SMEM_DYN);
    cudaFuncSetAttribute((const void*)hgemm<EpiFC1>,  cudaFuncAttributeMaxDynamicSharedMemorySize, SMEM_DYN);
    cudaFuncSetAttribute((const void*)hgemm<EpiFC2>,  cudaFuncAttributeMaxDynamicSharedMemorySize, SMEM_DYN);

    cvt_all<<<768, 256>>>(qkv_w, proj_w, fc1_w, fc2_w);
    bias_kernel<<<128, 256>>>(rpb);
    ln1_kernel<<<2048, 256>>>(x, norm1_g, norm1_b);
    hgemm<EpiQKV><<<dim3(6, 512), 256, SMEM_DYN>>>(p_xnw, pw_qkv, 256, EpiQKV{qkv_b});
    attn_mma<<<8192, 128>>>();
    gaze_conv_kernel<<<8192, 256>>>(gaze_w, gaze_b);
    hgemm<EpiProj><<<dim3(2, 512), 256, SMEM_DYN>>>(p_atth, pw_proj, 256, EpiProj{proj_b});
    ln2_kernel<<<8192, 256>>>(norm2_g, norm2_b);
    hgemm<EpiFC1><<<dim3(8, 512), 256, SMEM_DYN>>>(p_ln2, pw_fc1, 256, EpiFC1{fc1_b});
    hgemm<EpiFC2><<<dim3(2, 512), 256, SMEM_DYN>>>(p_h1, pw_fc2, 1024, EpiFC2{fc2_b, (float*)d_out});
}